// round 7
// baseline (speedup 1.0000x reference)
#include <cuda_runtime.h>
#include <cuda_bf16.h>
#include <cstdint>
#include <math.h>

// Problem dims
#define BATCH 64
#define SEQ   256
#define DIM   384
#define NHEAD 6
#define HDIM  64
#define NTOK  (BATCH * SEQ)      // 16384
#define FFDIM (4 * DIM)          // 1536

// ---------------- scratch (static device globals; no allocation) -------------
__device__ float g_h  [NTOK * DIM];
__device__ float g_q  [NTOK * DIM];
__device__ float g_k  [NTOK * DIM];
__device__ float g_v  [NTOK * DIM];
__device__ float g_ctx[NTOK * DIM];
__device__ float g_x1 [NTOK * DIM];
__device__ float g_ff [NTOK * FFDIM];
// transposed weights [M][K]
__device__ float g_wqT[DIM * DIM];
__device__ float g_wkT[DIM * DIM];
__device__ float g_wvT[DIM * DIM];
__device__ float g_woT[DIM * DIM];
__device__ float g_w1T[DIM * FFDIM];
__device__ float g_w2T[FFDIM * DIM];

// ---------------- PTX helpers -------------------------------------------------
__device__ __forceinline__ uint32_t smem_u32(const void* p) {
    uint32_t a;
    asm("{ .reg .u64 t; cvta.to.shared.u64 t, %1; cvt.u32.u64 %0, t; }"
        : "=r"(a) : "l"(p));
    return a;
}
__device__ __forceinline__ void cp_async16(uint32_t dst, const void* src) {
    asm volatile("cp.async.cg.shared.global [%0], [%1], 16;" :: "r"(dst), "l"(src));
}
__device__ __forceinline__ void cp_commit() {
    asm volatile("cp.async.commit_group;" ::: "memory");
}
template<int N> __device__ __forceinline__ void cp_wait() {
    asm volatile("cp.async.wait_group %0;" :: "n"(N) : "memory");
}
__device__ __forceinline__ void mma_tf32(float* c, const uint32_t* a, const uint32_t* b) {
    asm volatile(
        "mma.sync.aligned.m16n8k8.row.col.f32.tf32.tf32.f32 "
        "{%0,%1,%2,%3}, {%4,%5,%6,%7}, {%8,%9}, {%0,%1,%2,%3};"
        : "+f"(c[0]), "+f"(c[1]), "+f"(c[2]), "+f"(c[3])
        : "r"(a[0]), "r"(a[1]), "r"(a[2]), "r"(a[3]), "r"(b[0]), "r"(b[1]));
}
__device__ __forceinline__ void ldsm_x4(uint32_t& r0, uint32_t& r1, uint32_t& r2,
                                        uint32_t& r3, uint32_t addr) {
    asm volatile("ldmatrix.sync.aligned.m8n8.x4.shared.b16 {%0,%1,%2,%3}, [%4];"
                 : "=r"(r0), "=r"(r1), "=r"(r2), "=r"(r3) : "r"(addr));
}

// ================= tf32 mma.sync GEMM, cp.async 3-stage + ldmatrix ===========
// A: [N,K] row-major fp32. WT: [M,K] row-major (pre-transposed weights).
// C: [N,M] = act(A@W + bias + resid).
// CTA 128x128, BK=32, 8 warps (2x4), warp tile 64x32 (mt4 x nt4 m16n8k8).
// smem: A [128 rows][32 k] stride 36 floats; B [128 n][32 k] stride 36 floats.
// ldmatrix rows (16B) hit all 32 banks exactly once per 8-row tile.
#define BK       32
#define STRD     144                      // bytes per smem row (36 floats)
#define SA_BYTES (128 * STRD)             // 18432
#define SB_BYTES (128 * STRD)             // 18432
#define STAGE_BYTES (SA_BYTES + SB_BYTES) // 36864
#define STAGES   3
#define GEMM_SMEM (STAGES * STAGE_BYTES)  // 110592

template<bool RELU, bool BIAS, bool RESID>
__device__ __forceinline__ void gemm_body(
    uint32_t sb,
    const float* __restrict__ A, const float* __restrict__ WT,
    const float* __restrict__ bias, const float* __restrict__ resid,
    float* __restrict__ C, int K, int M, int row0, int col0)
{
    const int tid  = threadIdx.x;
    const int wid  = tid >> 5;
    const int lane = tid & 31;
    const int warpM = wid & 1;          // 64 rows
    const int warpN = wid >> 1;         // 32 cols
    const int g = lane >> 2, t = lane & 3;

    // ldmatrix per-lane source row/col offsets
    const int laneRowA = ((lane >> 3) & 1) * 8 + (lane & 7);
    const int laneKA   = (lane >> 4) * 16;          // bytes
    const int laneRowB = (lane >> 4) * 8 + (lane & 7);
    const int laneKB   = ((lane >> 3) & 1) * 16;    // bytes

    float acc[4][4][4];
#pragma unroll
    for (int mt = 0; mt < 4; mt++)
#pragma unroll
        for (int nt = 0; nt < 4; nt++)
#pragma unroll
            for (int f = 0; f < 4; f++) acc[mt][nt][f] = 0.f;

    const int KT = K >> 5;

    auto copy_stage = [&](int kt, int st) {
        const int k0 = kt << 5;
        const uint32_t abase = sb + st * STAGE_BYTES;
        const uint32_t bbase = abase + SA_BYTES;
#pragma unroll
        for (int i = 0; i < 4; i++) {
            int c = tid + (i << 8);                 // [0,1024)
            int r = c >> 3, k4 = c & 7;
            cp_async16(abase + r * STRD + (k4 << 4),
                       &A[(size_t)(row0 + r) * K + k0 + (k4 << 2)]);
        }
#pragma unroll
        for (int i = 0; i < 4; i++) {
            int c = tid + (i << 8);                 // [0,1024)
            int n = c >> 3, k4 = c & 7;
            cp_async16(bbase + n * STRD + (k4 << 4),
                       &WT[(size_t)(col0 + n) * K + k0 + (k4 << 2)]);
        }
    };

    copy_stage(0, 0); cp_commit();
    copy_stage(1, 1); cp_commit();

    for (int kt = 0; kt < KT; kt++) {
        const int st = kt % STAGES;
        if (kt + STAGES - 1 < KT) copy_stage(kt + STAGES - 1, (kt + STAGES - 1) % STAGES);
        cp_commit();
        cp_wait<STAGES - 1>();
        __syncthreads();

        const uint32_t aB = sb + st * STAGE_BYTES
                          + (warpM * 64 + laneRowA) * STRD + laneKA;
        const uint32_t bB = sb + st * STAGE_BYTES + SA_BYTES
                          + (warpN * 32 + laneRowB) * STRD + laneKB;
#pragma unroll
        for (int kc = 0; kc < 4; kc++) {
            uint32_t a_[4][4], b_[4][2];
#pragma unroll
            for (int mt = 0; mt < 4; mt++)
                ldsm_x4(a_[mt][0], a_[mt][1], a_[mt][2], a_[mt][3],
                        aB + mt * 16 * STRD + (kc << 5));
            ldsm_x4(b_[0][0], b_[0][1], b_[1][0], b_[1][1], bB + (kc << 5));
            ldsm_x4(b_[2][0], b_[2][1], b_[3][0], b_[3][1],
                    bB + 16 * STRD + (kc << 5));
#pragma unroll
            for (int mt = 0; mt < 4; mt++)
#pragma unroll
                for (int nt = 0; nt < 4; nt++)
                    mma_tf32(acc[mt][nt], a_[mt], b_[nt]);
        }
        __syncthreads();
    }

    // epilogue
#pragma unroll
    for (int mt = 0; mt < 4; mt++) {
        int r_lo = row0 + warpM * 64 + mt * 16 + g;
        int r_hi = r_lo + 8;
#pragma unroll
        for (int nt = 0; nt < 4; nt++) {
            int col = col0 + warpN * 32 + nt * 8 + (t << 1);
            float2 v0 = make_float2(acc[mt][nt][0], acc[mt][nt][1]);
            float2 v1 = make_float2(acc[mt][nt][2], acc[mt][nt][3]);
            if (BIAS) {
                float2 bv = *(const float2*)&bias[col];
                v0.x += bv.x; v0.y += bv.y;
                v1.x += bv.x; v1.y += bv.y;
            }
            if (RESID) {
                float2 q0 = *(const float2*)&resid[(size_t)r_lo * M + col];
                float2 q1 = *(const float2*)&resid[(size_t)r_hi * M + col];
                v0.x += q0.x; v0.y += q0.y;
                v1.x += q1.x; v1.y += q1.y;
            }
            if (RELU) {
                v0.x = fmaxf(v0.x, 0.f); v0.y = fmaxf(v0.y, 0.f);
                v1.x = fmaxf(v1.x, 0.f); v1.y = fmaxf(v1.y, 0.f);
            }
            *(float2*)&C[(size_t)r_lo * M + col] = v0;
            *(float2*)&C[(size_t)r_hi * M + col] = v1;
        }
    }
}

template<bool RELU, bool BIAS, bool RESID>
__global__ void __launch_bounds__(256, 2)
tf32_gemm_kernel(const float* __restrict__ A, const float* __restrict__ WT,
                 const float* __restrict__ bias, const float* __restrict__ resid,
                 float* __restrict__ C, int K, int M)
{
    extern __shared__ char smem[];
    gemm_body<RELU, BIAS, RESID>(smem_u32(smem), A, WT, bias, resid, C, K, M,
                                 blockIdx.x * 128, blockIdx.y * 128);
}

// Fused QKV: blockIdx.y in [0,9): sel = y/3 picks weight/output, (y%3)*128 col.
__global__ void __launch_bounds__(256, 2)
qkv_gemm_kernel(const float* __restrict__ A,
                const float* __restrict__ wqT, const float* __restrict__ wkT,
                const float* __restrict__ wvT,
                float* __restrict__ q, float* __restrict__ k, float* __restrict__ v)
{
    extern __shared__ char smem[];
    int y = blockIdx.y;
    int sel = y / 3;
    int col0 = (y - sel * 3) * 128;
    const float* WT = (sel == 0) ? wqT : (sel == 1) ? wkT : wvT;
    float* C = (sel == 0) ? q : (sel == 1) ? k : v;
    gemm_body<false, false, false>(smem_u32(smem), A, WT, nullptr, nullptr, C,
                                   DIM, DIM, blockIdx.x * 128, col0);
}

// ---------------- weight transposes ------------------------------------------
// in[R][C] -> out[C][R]; R, C multiples of 32. block (32,8).
__device__ __forceinline__ void transpose_tile(const float* in, float* out,
                                               int R, int C)
{
    __shared__ float t[32][33];
    int bx = blockIdx.x * 32, by = blockIdx.y * 32;
#pragma unroll
    for (int i = 0; i < 32; i += 8)
        t[threadIdx.y + i][threadIdx.x] =
            in[(size_t)(by + threadIdx.y + i) * C + bx + threadIdx.x];
    __syncthreads();
#pragma unroll
    for (int i = 0; i < 32; i += 8)
        out[(size_t)(bx + threadIdx.y + i) * R + by + threadIdx.x] =
            t[threadIdx.x][threadIdx.y + i];
}
__global__ void transpose4_kernel(const float* w0, const float* w1,
                                  const float* w2, const float* w3,
                                  float* o0, float* o1, float* o2, float* o3)
{
    const float* in; float* out;
    switch (blockIdx.z) {
        case 0: in = w0; out = o0; break;
        case 1: in = w1; out = o1; break;
        case 2: in = w2; out = o2; break;
        default: in = w3; out = o3; break;
    }
    transpose_tile(in, out, DIM, DIM);
}
__global__ void transpose_kernel(const float* in, float* out, int R, int C)
{
    transpose_tile(in, out, R, C);
}

// ---------------- LayerNorm: one warp per token ------------------------------
__global__ void ln_kernel(const float* __restrict__ x,
                          const float* __restrict__ g,
                          const float* __restrict__ be,
                          float* __restrict__ out)
{
    int warp = (blockIdx.x * blockDim.x + threadIdx.x) >> 5;
    int lane = threadIdx.x & 31;
    if (warp >= NTOK) return;
    const float* row = x + (size_t)warp * DIM;
    float v[12];
    float s = 0.f, ss = 0.f;
#pragma unroll
    for (int i = 0; i < 12; i++) {
        v[i] = row[lane + 32 * i];
        s  += v[i];
        ss += v[i] * v[i];
    }
#pragma unroll
    for (int o = 16; o; o >>= 1) {
        s  += __shfl_xor_sync(0xffffffffu, s, o);
        ss += __shfl_xor_sync(0xffffffffu, ss, o);
    }
    float mean = s * (1.0f / DIM);
    float var  = ss * (1.0f / DIM) - mean * mean;
    float rstd = rsqrtf(var + 1e-5f);
    float* orow = out + (size_t)warp * DIM;
#pragma unroll
    for (int i = 0; i < 12; i++) {
        int c = lane + 32 * i;
        orow[c] = (v[i] - mean) * rstd * g[c] + be[c];
    }
}

// ---------------- Causal flash attention (fp32) ------------------------------
__global__ void __launch_bounds__(256)
attn_kernel(const float* __restrict__ q, const float* __restrict__ k,
            const float* __restrict__ v, float* __restrict__ ctx)
{
    extern __shared__ float sm[];
    float* Qst   = sm;
    float* Kst   = Qst + 64 * 64;
    float* Vs    = Kst + 64 * 64;
    float* Ss    = Vs + 64 * 64;
    float* alphas = Ss + 64 * 65;
    float* m_s   = alphas + 64;
    float* l_s   = m_s + 64;

    int qt = blockIdx.x;
    int h  = blockIdx.y;
    int b  = blockIdx.z;
    int tid = threadIdx.x;
    int tx = tid & 15, ty = tid >> 4;

    const float* qbase = q + (size_t)b * SEQ * DIM + h * HDIM;
    const float* kbase = k + (size_t)b * SEQ * DIM + h * HDIM;
    const float* vbase = v + (size_t)b * SEQ * DIM + h * HDIM;

#pragma unroll
    for (int i = 0; i < 4; i++) {
        int f = tid + i * 256;
        int r = f >> 4, d4 = (f & 15) << 2;
        float4 val = *(const float4*)&qbase[(size_t)(qt * 64 + r) * DIM + d4];
        Qst[(d4 + 0) * 64 + r] = val.x;
        Qst[(d4 + 1) * 64 + r] = val.y;
        Qst[(d4 + 2) * 64 + r] = val.z;
        Qst[(d4 + 3) * 64 + r] = val.w;
    }
    if (tid < 64) { m_s[tid] = -1e30f; l_s[tid] = 0.f; }

    float o[4][4] = {{0.f}};

    for (int kt = 0; kt <= qt; kt++) {
        __syncthreads();
#pragma unroll
        for (int i = 0; i < 4; i++) {
            int f = tid + i * 256;
            int r = f >> 4, d4 = (f & 15) << 2;
            float4 val = *(const float4*)&kbase[(size_t)(kt * 64 + r) * DIM + d4];
            Kst[(d4 + 0) * 64 + r] = val.x;
            Kst[(d4 + 1) * 64 + r] = val.y;
            Kst[(d4 + 2) * 64 + r] = val.z;
            Kst[(d4 + 3) * 64 + r] = val.w;
        }
        __syncthreads();

        float s_[4][4] = {{0.f}};
#pragma unroll
        for (int d = 0; d < 64; d++) {
            float4 a  = *(float4*)&Qst[d * 64 + ty * 4];
            float4 bq = *(float4*)&Kst[d * 64 + tx * 4];
            s_[0][0] += a.x * bq.x; s_[0][1] += a.x * bq.y; s_[0][2] += a.x * bq.z; s_[0][3] += a.x * bq.w;
            s_[1][0] += a.y * bq.x; s_[1][1] += a.y * bq.y; s_[1][2] += a.y * bq.z; s_[1][3] += a.y * bq.w;
            s_[2][0] += a.z * bq.x; s_[2][1] += a.z * bq.y; s_[2][2] += a.z * bq.z; s_[2][3] += a.z * bq.w;
            s_[3][0] += a.w * bq.x; s_[3][1] += a.w * bq.y; s_[3][2] += a.w * bq.z; s_[3][3] += a.w * bq.w;
        }
#pragma unroll
        for (int i = 0; i < 4; i++) {
#pragma unroll
            for (int j = 0; j < 4; j++) {
                int qi = ty * 4 + i, kj = tx * 4 + j;
                float val = s_[i][j] * 0.125f;
                if (kt * 64 + kj > qt * 64 + qi) val = -1e30f;
                Ss[qi * 65 + kj] = val;
            }
        }
        __syncthreads();

#pragma unroll
        for (int i = 0; i < 4; i++) {
            int f = tid + i * 256;
            int r = f >> 4, d4 = (f & 15) << 2;
            float4 val = *(const float4*)&vbase[(size_t)(kt * 64 + r) * DIM + d4];
            *(float4*)&Vs[r * 64 + d4] = val;
        }
        if (tid < 64) {
            float m_old = m_s[tid];
            float mt = m_old;
#pragma unroll 8
            for (int c = 0; c < 64; c++) mt = fmaxf(mt, Ss[tid * 65 + c]);
            float alpha = __expf(m_old - mt);
            float sum = 0.f;
#pragma unroll 8
            for (int c = 0; c < 64; c++) {
                float p = __expf(Ss[tid * 65 + c] - mt);
                Ss[tid * 65 + c] = p;
                sum += p;
            }
            m_s[tid] = mt;
            l_s[tid] = l_s[tid] * alpha + sum;
            alphas[tid] = alpha;
        }
        __syncthreads();

#pragma unroll
        for (int i = 0; i < 4; i++) {
            float al = alphas[ty * 4 + i];
            o[i][0] *= al; o[i][1] *= al; o[i][2] *= al; o[i][3] *= al;
        }
#pragma unroll
        for (int kk = 0; kk < 64; kk++) {
            float4 bv = *(float4*)&Vs[kk * 64 + tx * 4];
            float a0 = Ss[(ty * 4 + 0) * 65 + kk];
            float a1 = Ss[(ty * 4 + 1) * 65 + kk];
            float a2 = Ss[(ty * 4 + 2) * 65 + kk];
            float a3 = Ss[(ty * 4 + 3) * 65 + kk];
            o[0][0] += a0 * bv.x; o[0][1] += a0 * bv.y; o[0][2] += a0 * bv.z; o[0][3] += a0 * bv.w;
            o[1][0] += a1 * bv.x; o[1][1] += a1 * bv.y; o[1][2] += a1 * bv.z; o[1][3] += a1 * bv.w;
            o[2][0] += a2 * bv.x; o[2][1] += a2 * bv.y; o[2][2] += a2 * bv.z; o[2][3] += a2 * bv.w;
            o[3][0] += a3 * bv.x; o[3][1] += a3 * bv.y; o[3][2] += a3 * bv.z; o[3][3] += a3 * bv.w;
        }
    }

    float* obase = ctx + (size_t)b * SEQ * DIM + h * HDIM;
#pragma unroll
    for (int i = 0; i < 4; i++) {
        int qi = ty * 4 + i;
        float inv_l = 1.0f / l_s[qi];
        float4 val;
        val.x = o[i][0] * inv_l;
        val.y = o[i][1] * inv_l;
        val.z = o[i][2] * inv_l;
        val.w = o[i][3] * inv_l;
        *(float4*)&obase[(size_t)(qt * 64 + qi) * DIM + tx * 4] = val;
    }
}

// ---------------- launch ------------------------------------------------------
static float* dev_ptr(const void* sym)
{
    void* p = nullptr;
    cudaGetSymbolAddress(&p, sym);
    return (float*)p;
}

extern "C" void kernel_launch(void* const* d_in, const int* in_sizes, int n_in,
                              void* d_out, int out_size)
{
    (void)in_sizes; (void)n_in; (void)out_size;
    const float* x   = (const float*)d_in[0];
    const float* wq  = (const float*)d_in[1];
    const float* wk  = (const float*)d_in[2];
    const float* wv  = (const float*)d_in[3];
    const float* wo  = (const float*)d_in[4];
    const float* bo  = (const float*)d_in[5];
    const float* w1  = (const float*)d_in[6];
    const float* b1  = (const float*)d_in[7];
    const float* w2  = (const float*)d_in[8];
    const float* b2  = (const float*)d_in[9];
    const float* g1  = (const float*)d_in[10];
    const float* be1 = (const float*)d_in[11];
    const float* g2  = (const float*)d_in[12];
    const float* be2 = (const float*)d_in[13];
    float* out = (float*)d_out;

    float* h    = dev_ptr(g_h);
    float* qb   = dev_ptr(g_q);
    float* kb   = dev_ptr(g_k);
    float* vb   = dev_ptr(g_v);
    float* ctx  = dev_ptr(g_ctx);
    float* x1   = dev_ptr(g_x1);
    float* ff   = dev_ptr(g_ff);
    float* wqT  = dev_ptr(g_wqT);
    float* wkT  = dev_ptr(g_wkT);
    float* wvT  = dev_ptr(g_wvT);
    float* woT  = dev_ptr(g_woT);
    float* w1T  = dev_ptr(g_w1T);
    float* w2T  = dev_ptr(g_w2T);

    const int ATTN_SMEM = (64 * 64 * 3 + 64 * 65 + 64 * 3) * sizeof(float); // 66560
    cudaFuncSetAttribute(attn_kernel, cudaFuncAttributeMaxDynamicSharedMemorySize, ATTN_SMEM);
    cudaFuncSetAttribute(qkv_gemm_kernel,
                         cudaFuncAttributeMaxDynamicSharedMemorySize, GEMM_SMEM);
    cudaFuncSetAttribute(tf32_gemm_kernel<false, true, true>,
                         cudaFuncAttributeMaxDynamicSharedMemorySize, GEMM_SMEM);
    cudaFuncSetAttribute(tf32_gemm_kernel<true, true, false>,
                         cudaFuncAttributeMaxDynamicSharedMemorySize, GEMM_SMEM);

    // transpose all weights (runs concurrently with LN1 — no dependency)
    transpose4_kernel<<<dim3(12, 12, 4), dim3(32, 8)>>>(wq, wk, wv, wo,
                                                        wqT, wkT, wvT, woT);
    transpose_kernel<<<dim3(FFDIM / 32, DIM / 32), dim3(32, 8)>>>(w1, w1T, DIM, FFDIM);
    transpose_kernel<<<dim3(DIM / 32, FFDIM / 32), dim3(32, 8)>>>(w2, w2T, FFDIM, DIM);

    // LN1
    ln_kernel<<<NTOK / 8, 256>>>(x, g1, be1, h);
    // fused QKV projections
    qkv_gemm_kernel<<<dim3(NTOK / 128, 9), 256, GEMM_SMEM>>>(h, wqT, wkT, wvT, qb, kb, vb);
    // attention (fp32)
    attn_kernel<<<dim3(SEQ / 64, NHEAD, BATCH), 256, ATTN_SMEM>>>(qb, kb, vb, ctx);
    // output projection + residual
    tf32_gemm_kernel<false, true, true><<<dim3(NTOK / 128, 3), 256, GEMM_SMEM>>>(ctx, woT, bo, x, x1, DIM, DIM);
    // LN2
    ln_kernel<<<NTOK / 8, 256>>>(x1, g2, be2, h);
    // FFN
    tf32_gemm_kernel<true, true, false><<<dim3(NTOK / 128, 12), 256, GEMM_SMEM>>>(h, w1T, b1, nullptr, ff, DIM, FFDIM);
    tf32_gemm_kernel<false, true, true><<<dim3(NTOK / 128, 3), 256, GEMM_SMEM>>>(ff, w2T, b2, x1, out, FFDIM, DIM);
}

// round 8
// speedup vs baseline: 1.2242x; 1.2242x over previous
#include <cuda_runtime.h>
#include <cuda_bf16.h>
#include <cstdint>
#include <math.h>

// Problem dims
#define BATCH 64
#define SEQ   256
#define DIM   384
#define NHEAD 6
#define HDIM  64
#define NTOK  (BATCH * SEQ)      // 16384
#define FFDIM (4 * DIM)          // 1536

// ---------------- scratch (static device globals; no allocation) -------------
__device__ float g_h  [NTOK * DIM];
__device__ float g_q  [NTOK * DIM];
__device__ float g_k  [NTOK * DIM];
__device__ float g_v  [NTOK * DIM];
__device__ float g_ctx[NTOK * DIM];
__device__ float g_x1 [NTOK * DIM];
__device__ float g_ff [NTOK * FFDIM];
// transposed weights [M][K]
__device__ float g_wqT[DIM * DIM];
__device__ float g_wkT[DIM * DIM];
__device__ float g_wvT[DIM * DIM];
__device__ float g_woT[DIM * DIM];
__device__ float g_w1T[DIM * FFDIM];
__device__ float g_w2T[FFDIM * DIM];

// ---------------- PTX helpers -------------------------------------------------
__device__ __forceinline__ uint32_t smem_u32(const void* p) {
    uint32_t a;
    asm("{ .reg .u64 t; cvta.to.shared.u64 t, %1; cvt.u32.u64 %0, t; }"
        : "=r"(a) : "l"(p));
    return a;
}
__device__ __forceinline__ void cp_async16(uint32_t dst, const void* src) {
    asm volatile("cp.async.cg.shared.global [%0], [%1], 16;" :: "r"(dst), "l"(src));
}
__device__ __forceinline__ void cp_commit() {
    asm volatile("cp.async.commit_group;" ::: "memory");
}
template<int N> __device__ __forceinline__ void cp_wait() {
    asm volatile("cp.async.wait_group %0;" :: "n"(N) : "memory");
}
__device__ __forceinline__ void mma_tf32(float* c, const uint32_t* a, const uint32_t* b) {
    asm volatile(
        "mma.sync.aligned.m16n8k8.row.col.f32.tf32.tf32.f32 "
        "{%0,%1,%2,%3}, {%4,%5,%6,%7}, {%8,%9}, {%0,%1,%2,%3};"
        : "+f"(c[0]), "+f"(c[1]), "+f"(c[2]), "+f"(c[3])
        : "r"(a[0]), "r"(a[1]), "r"(a[2]), "r"(a[3]), "r"(b[0]), "r"(b[1]));
}
__device__ __forceinline__ void ldsm_x4(uint32_t& r0, uint32_t& r1, uint32_t& r2,
                                        uint32_t& r3, uint32_t addr) {
    asm volatile("ldmatrix.sync.aligned.m8n8.x4.shared.b16 {%0,%1,%2,%3}, [%4];"
                 : "=r"(r0), "=r"(r1), "=r"(r2), "=r"(r3) : "r"(addr));
}
__device__ __forceinline__ uint32_t lds32(uint32_t addr) {
    uint32_t v;
    asm volatile("ld.shared.b32 %0, [%1];" : "=r"(v) : "r"(addr));
    return v;
}

// ================= tf32 mma.sync GEMM, cp.async 3-stage + ldmatrix ===========
#define BK       32
#define STRD     144                      // bytes per smem row (36 floats)
#define SA_BYTES (128 * STRD)             // 18432
#define SB_BYTES (128 * STRD)             // 18432
#define STAGE_BYTES (SA_BYTES + SB_BYTES) // 36864
#define STAGES   3
#define GEMM_SMEM (STAGES * STAGE_BYTES)  // 110592

template<bool RELU, bool BIAS, bool RESID>
__device__ __forceinline__ void gemm_body(
    uint32_t sb,
    const float* __restrict__ A, const float* __restrict__ WT,
    const float* __restrict__ bias, const float* __restrict__ resid,
    float* __restrict__ C, int K, int M, int row0, int col0)
{
    const int tid  = threadIdx.x;
    const int wid  = tid >> 5;
    const int lane = tid & 31;
    const int warpM = wid & 1;
    const int warpN = wid >> 1;
    const int g = lane >> 2, t = lane & 3;

    const int laneRowA = ((lane >> 3) & 1) * 8 + (lane & 7);
    const int laneKA   = (lane >> 4) * 16;
    const int laneRowB = (lane >> 4) * 8 + (lane & 7);
    const int laneKB   = ((lane >> 3) & 1) * 16;

    float acc[4][4][4];
#pragma unroll
    for (int mt = 0; mt < 4; mt++)
#pragma unroll
        for (int nt = 0; nt < 4; nt++)
#pragma unroll
            for (int f = 0; f < 4; f++) acc[mt][nt][f] = 0.f;

    const int KT = K >> 5;

    auto copy_stage = [&](int kt, int st) {
        const int k0 = kt << 5;
        const uint32_t abase = sb + st * STAGE_BYTES;
        const uint32_t bbase = abase + SA_BYTES;
#pragma unroll
        for (int i = 0; i < 4; i++) {
            int c = tid + (i << 8);
            int r = c >> 3, k4 = c & 7;
            cp_async16(abase + r * STRD + (k4 << 4),
                       &A[(size_t)(row0 + r) * K + k0 + (k4 << 2)]);
        }
#pragma unroll
        for (int i = 0; i < 4; i++) {
            int c = tid + (i << 8);
            int n = c >> 3, k4 = c & 7;
            cp_async16(bbase + n * STRD + (k4 << 4),
                       &WT[(size_t)(col0 + n) * K + k0 + (k4 << 2)]);
        }
    };

    copy_stage(0, 0); cp_commit();
    copy_stage(1, 1); cp_commit();

    for (int kt = 0; kt < KT; kt++) {
        const int st = kt % STAGES;
        if (kt + STAGES - 1 < KT) copy_stage(kt + STAGES - 1, (kt + STAGES - 1) % STAGES);
        cp_commit();
        cp_wait<STAGES - 1>();
        __syncthreads();

        const uint32_t aB = sb + st * STAGE_BYTES
                          + (warpM * 64 + laneRowA) * STRD + laneKA;
        const uint32_t bB = sb + st * STAGE_BYTES + SA_BYTES
                          + (warpN * 32 + laneRowB) * STRD + laneKB;
#pragma unroll
        for (int kc = 0; kc < 4; kc++) {
            uint32_t a_[4][4], b_[4][2];
#pragma unroll
            for (int mt = 0; mt < 4; mt++)
                ldsm_x4(a_[mt][0], a_[mt][1], a_[mt][2], a_[mt][3],
                        aB + mt * 16 * STRD + (kc << 5));
            ldsm_x4(b_[0][0], b_[0][1], b_[1][0], b_[1][1], bB + (kc << 5));
            ldsm_x4(b_[2][0], b_[2][1], b_[3][0], b_[3][1],
                    bB + 16 * STRD + (kc << 5));
#pragma unroll
            for (int mt = 0; mt < 4; mt++)
#pragma unroll
                for (int nt = 0; nt < 4; nt++)
                    mma_tf32(acc[mt][nt], a_[mt], b_[nt]);
        }
        __syncthreads();
    }

#pragma unroll
    for (int mt = 0; mt < 4; mt++) {
        int r_lo = row0 + warpM * 64 + mt * 16 + g;
        int r_hi = r_lo + 8;
#pragma unroll
        for (int nt = 0; nt < 4; nt++) {
            int col = col0 + warpN * 32 + nt * 8 + (t << 1);
            float2 v0 = make_float2(acc[mt][nt][0], acc[mt][nt][1]);
            float2 v1 = make_float2(acc[mt][nt][2], acc[mt][nt][3]);
            if (BIAS) {
                float2 bv = *(const float2*)&bias[col];
                v0.x += bv.x; v0.y += bv.y;
                v1.x += bv.x; v1.y += bv.y;
            }
            if (RESID) {
                float2 q0 = *(const float2*)&resid[(size_t)r_lo * M + col];
                float2 q1 = *(const float2*)&resid[(size_t)r_hi * M + col];
                v0.x += q0.x; v0.y += q0.y;
                v1.x += q1.x; v1.y += q1.y;
            }
            if (RELU) {
                v0.x = fmaxf(v0.x, 0.f); v0.y = fmaxf(v0.y, 0.f);
                v1.x = fmaxf(v1.x, 0.f); v1.y = fmaxf(v1.y, 0.f);
            }
            *(float2*)&C[(size_t)r_lo * M + col] = v0;
            *(float2*)&C[(size_t)r_hi * M + col] = v1;
        }
    }
}

template<bool RELU, bool BIAS, bool RESID>
__global__ void __launch_bounds__(256, 2)
tf32_gemm_kernel(const float* __restrict__ A, const float* __restrict__ WT,
                 const float* __restrict__ bias, const float* __restrict__ resid,
                 float* __restrict__ C, int K, int M)
{
    extern __shared__ char smem[];
    gemm_body<RELU, BIAS, RESID>(smem_u32(smem), A, WT, bias, resid, C, K, M,
                                 blockIdx.x * 128, blockIdx.y * 128);
}

__global__ void __launch_bounds__(256, 2)
qkv_gemm_kernel(const float* __restrict__ A,
                const float* __restrict__ wqT, const float* __restrict__ wkT,
                const float* __restrict__ wvT,
                float* __restrict__ q, float* __restrict__ k, float* __restrict__ v)
{
    extern __shared__ char smem[];
    int y = blockIdx.y;
    int sel = y / 3;
    int col0 = (y - sel * 3) * 128;
    const float* WT = (sel == 0) ? wqT : (sel == 1) ? wkT : wvT;
    float* C = (sel == 0) ? q : (sel == 1) ? k : v;
    gemm_body<false, false, false>(smem_u32(smem), A, WT, nullptr, nullptr, C,
                                   DIM, DIM, blockIdx.x * 128, col0);
}

// ---------------- weight transposes ------------------------------------------
__device__ __forceinline__ void transpose_tile(const float* in, float* out,
                                               int R, int C)
{
    __shared__ float t[32][33];
    int bx = blockIdx.x * 32, by = blockIdx.y * 32;
#pragma unroll
    for (int i = 0; i < 32; i += 8)
        t[threadIdx.y + i][threadIdx.x] =
            in[(size_t)(by + threadIdx.y + i) * C + bx + threadIdx.x];
    __syncthreads();
#pragma unroll
    for (int i = 0; i < 32; i += 8)
        out[(size_t)(bx + threadIdx.y + i) * R + by + threadIdx.x] =
            t[threadIdx.x][threadIdx.y + i];
}
__global__ void transpose4_kernel(const float* w0, const float* w1,
                                  const float* w2, const float* w3,
                                  float* o0, float* o1, float* o2, float* o3)
{
    const float* in; float* out;
    switch (blockIdx.z) {
        case 0: in = w0; out = o0; break;
        case 1: in = w1; out = o1; break;
        case 2: in = w2; out = o2; break;
        default: in = w3; out = o3; break;
    }
    transpose_tile(in, out, DIM, DIM);
}
__global__ void transpose_kernel(const float* in, float* out, int R, int C)
{
    transpose_tile(in, out, R, C);
}

// ---------------- LayerNorm ----------------------------------------------------
__global__ void ln_kernel(const float* __restrict__ x,
                          const float* __restrict__ g,
                          const float* __restrict__ be,
                          float* __restrict__ out)
{
    int warp = (blockIdx.x * blockDim.x + threadIdx.x) >> 5;
    int lane = threadIdx.x & 31;
    if (warp >= NTOK) return;
    const float* row = x + (size_t)warp * DIM;
    float v[12];
    float s = 0.f, ss = 0.f;
#pragma unroll
    for (int i = 0; i < 12; i++) {
        v[i] = row[lane + 32 * i];
        s  += v[i];
        ss += v[i] * v[i];
    }
#pragma unroll
    for (int o = 16; o; o >>= 1) {
        s  += __shfl_xor_sync(0xffffffffu, s, o);
        ss += __shfl_xor_sync(0xffffffffu, ss, o);
    }
    float mean = s * (1.0f / DIM);
    float var  = ss * (1.0f / DIM) - mean * mean;
    float rstd = rsqrtf(var + 1e-5f);
    float* orow = out + (size_t)warp * DIM;
#pragma unroll
    for (int i = 0; i < 12; i++) {
        int c = lane + 32 * i;
        orow[c] = (v[i] - mean) * rstd * g[c] + be[c];
    }
}

// ---------------- Tensor-core causal flash attention --------------------------
// CTA = (qt, h, b): 64 queries. 128 threads (4 warps x 16 q-rows).
// smem (floats, stride 68/row): Q[64][68], P[64][68], 2 stages x (K[64][68],
// V[64][68]), then m/l/alpha[64] each.
// Fragment maps (m16n8k8 tf32, g=lane>>2, t=lane&3):
//   A: a0(g,t) a1(g+8,t) a2(g,t+4) a3(g+8,t+4)
//   B: b0(k=t,n=g) b1(k=t+4,n=g)
//   C: c0(g,2t) c1(g,2t+1) c2(g+8,2t) c3(g+8,2t+1)
#define AT_RS    68                        // floats per row
#define AT_RB    (AT_RS * 4)               // 272 bytes per row
#define AT_TILE  (64 * AT_RB)              // 17408 bytes per 64x68 tile
#define AT_QOFF  0
#define AT_POFF  AT_TILE
#define AT_KVOFF (2 * AT_TILE)
#define AT_STAGE (2 * AT_TILE)             // K + V per stage
#define AT_MOFF  (AT_KVOFF + 2 * AT_STAGE) // 104448
#define ATTN_SMEM (AT_MOFF + 3 * 64 * 4)   // 105216

__global__ void __launch_bounds__(128, 2)
attn_mma_kernel(const float* __restrict__ q, const float* __restrict__ k,
                const float* __restrict__ v, float* __restrict__ ctx)
{
    extern __shared__ float sm[];
    const uint32_t sb = smem_u32(sm);

    const int qt = blockIdx.x;
    const int h  = blockIdx.y;
    const int b  = blockIdx.z;
    const int tid = threadIdx.x;
    const int wid = tid >> 5;
    const int lane = tid & 31;
    const int g = lane >> 2, t = lane & 3;
    const int w16 = wid * 16;

    const float* qbase = q + (size_t)b * SEQ * DIM + h * HDIM;
    const float* kbase = k + (size_t)b * SEQ * DIM + h * HDIM;
    const float* vbase = v + (size_t)b * SEQ * DIM + h * HDIM;

    // Q tile: 64 rows x 16 float4 = 1024 f4, 8 per thread (cp.async)
#pragma unroll
    for (int i = 0; i < 8; i++) {
        int f = tid + (i << 7);
        int r = f >> 4, d4 = (f & 15) << 2;
        cp_async16(sb + AT_QOFF + r * AT_RB + (d4 << 2),
                   &qbase[(size_t)(qt * 64 + r) * DIM + d4]);
    }
    auto copy_kv = [&](int kt, int st) {
        const uint32_t kdst = sb + AT_KVOFF + st * AT_STAGE;
        const uint32_t vdst = kdst + AT_TILE;
#pragma unroll
        for (int i = 0; i < 8; i++) {
            int f = tid + (i << 7);
            int r = f >> 4, d4 = (f & 15) << 2;
            cp_async16(kdst + r * AT_RB + (d4 << 2),
                       &kbase[(size_t)(kt * 64 + r) * DIM + d4]);
        }
#pragma unroll
        for (int i = 0; i < 8; i++) {
            int f = tid + (i << 7);
            int r = f >> 4, d4 = (f & 15) << 2;
            cp_async16(vdst + r * AT_RB + (d4 << 2),
                       &vbase[(size_t)(kt * 64 + r) * DIM + d4]);
        }
    };

    copy_kv(0, 0);
    cp_commit();
    if (tid < 64) {
        sm[AT_MOFF / 4 + tid] = -1e30f;          // m
        sm[AT_MOFF / 4 + 64 + tid] = 0.f;        // l
    }

    float accO[8][4];
#pragma unroll
    for (int nt = 0; nt < 8; nt++)
#pragma unroll
        for (int f = 0; f < 4; f++) accO[nt][f] = 0.f;

    const int KT = qt + 1;
    for (int kt = 0; kt < KT; kt++) {
        const int st = kt & 1;
        if (kt + 1 < KT) copy_kv(kt + 1, st ^ 1);
        cp_commit();
        cp_wait<1>();
        __syncthreads();

        // ---- S = Q @ K^T ----
        float accS[8][4];
#pragma unroll
        for (int nt = 0; nt < 8; nt++)
#pragma unroll
            for (int f = 0; f < 4; f++) accS[nt][f] = 0.f;

        const uint32_t aQ = sb + AT_QOFF + (w16 + g) * AT_RB + (t << 2);
        const uint32_t bK = sb + AT_KVOFF + st * AT_STAGE + g * AT_RB + (t << 2);
#pragma unroll
        for (int kc = 0; kc < 8; kc++) {
            uint32_t a_[4];
            a_[0] = lds32(aQ + (kc << 5));
            a_[1] = lds32(aQ + 8 * AT_RB + (kc << 5));
            a_[2] = lds32(aQ + (kc << 5) + 16);
            a_[3] = lds32(aQ + 8 * AT_RB + (kc << 5) + 16);
#pragma unroll
            for (int nt = 0; nt < 8; nt++) {
                uint32_t b_[2];
                uint32_t ba = bK + nt * 8 * AT_RB + (kc << 5);
                b_[0] = lds32(ba);
                b_[1] = lds32(ba + 16);
                mma_tf32(accS[nt], a_, b_);
            }
        }

        // ---- mask + scale + store S to P smem ----
        {
            const int r0 = w16 + g, r1 = r0 + 8;
            const int gq0 = qt * 64 + r0, gq1 = qt * 64 + r1;
            float* p0 = &sm[AT_POFF / 4 + r0 * AT_RS];
            float* p1 = &sm[AT_POFF / 4 + r1 * AT_RS];
#pragma unroll
            for (int nt = 0; nt < 8; nt++) {
                int c = nt * 8 + (t << 1);
                int gk0 = kt * 64 + c, gk1 = gk0 + 1;
                float s0 = (gk0 > gq0) ? -1e30f : accS[nt][0] * 0.125f;
                float s1 = (gk1 > gq0) ? -1e30f : accS[nt][1] * 0.125f;
                float s2 = (gk0 > gq1) ? -1e30f : accS[nt][2] * 0.125f;
                float s3 = (gk1 > gq1) ? -1e30f : accS[nt][3] * 0.125f;
                *(float2*)&p0[c] = make_float2(s0, s1);
                *(float2*)&p1[c] = make_float2(s2, s3);
            }
        }
        __syncthreads();

        // ---- softmax: 2 threads per row ----
        {
            const int row = tid >> 1, half = tid & 1;
            float* prow = &sm[AT_POFF / 4 + row * AT_RS + half * 32];
            float vals[32];
#pragma unroll
            for (int i = 0; i < 8; i++) {
                float4 x4 = *(float4*)&prow[i * 4];
                vals[i * 4 + 0] = x4.x; vals[i * 4 + 1] = x4.y;
                vals[i * 4 + 2] = x4.z; vals[i * 4 + 3] = x4.w;
            }
            float mt = -1e30f;
#pragma unroll
            for (int i = 0; i < 32; i++) mt = fmaxf(mt, vals[i]);
            mt = fmaxf(mt, __shfl_xor_sync(0xffffffffu, mt, 1));
            float m_old = sm[AT_MOFF / 4 + row];
            float mn = fmaxf(m_old, mt);
            float sum = 0.f;
#pragma unroll
            for (int i = 0; i < 32; i++) {
                float p = __expf(vals[i] - mn);
                vals[i] = p;
                sum += p;
            }
#pragma unroll
            for (int i = 0; i < 8; i++)
                *(float4*)&prow[i * 4] = make_float4(vals[i * 4 + 0], vals[i * 4 + 1],
                                                     vals[i * 4 + 2], vals[i * 4 + 3]);
            sum += __shfl_xor_sync(0xffffffffu, sum, 1);
            if (half == 0) {
                float alpha = __expf(m_old - mn);
                sm[AT_MOFF / 4 + row] = mn;
                sm[AT_MOFF / 4 + 64 + row] = sm[AT_MOFF / 4 + 64 + row] * alpha + sum;
                sm[AT_MOFF / 4 + 128 + row] = alpha;
            }
        }
        __syncthreads();

        // ---- O = O*alpha + P @ V ----
        {
            float al0 = sm[AT_MOFF / 4 + 128 + w16 + g];
            float al1 = sm[AT_MOFF / 4 + 128 + w16 + g + 8];
#pragma unroll
            for (int nt = 0; nt < 8; nt++) {
                accO[nt][0] *= al0; accO[nt][1] *= al0;
                accO[nt][2] *= al1; accO[nt][3] *= al1;
            }
            const uint32_t aP = sb + AT_POFF + (w16 + g) * AT_RB + (t << 2);
            const uint32_t bV = sb + AT_KVOFF + st * AT_STAGE + AT_TILE
                              + t * AT_RB + (g << 2);
#pragma unroll
            for (int kc = 0; kc < 8; kc++) {
                uint32_t a_[4];
                a_[0] = lds32(aP + (kc << 5));
                a_[1] = lds32(aP + 8 * AT_RB + (kc << 5));
                a_[2] = lds32(aP + (kc << 5) + 16);
                a_[3] = lds32(aP + 8 * AT_RB + (kc << 5) + 16);
#pragma unroll
                for (int nt = 0; nt < 8; nt++) {
                    uint32_t b_[2];
                    uint32_t ba = bV + kc * 8 * AT_RB + (nt << 5);
                    b_[0] = lds32(ba);
                    b_[1] = lds32(ba + 4 * AT_RB);
                    mma_tf32(accO[nt], a_, b_);
                }
            }
        }
        __syncthreads();
    }

    // ---- write ctx = O / l ----
    {
        const int r0 = w16 + g, r1 = r0 + 8;
        float inv0 = 1.0f / sm[AT_MOFF / 4 + 64 + r0];
        float inv1 = 1.0f / sm[AT_MOFF / 4 + 64 + r1];
        float* obase = ctx + (size_t)b * SEQ * DIM + h * HDIM;
        float* o0 = &obase[(size_t)(qt * 64 + r0) * DIM];
        float* o1 = &obase[(size_t)(qt * 64 + r1) * DIM];
#pragma unroll
        for (int nt = 0; nt < 8; nt++) {
            int c = nt * 8 + (t << 1);
            *(float2*)&o0[c] = make_float2(accO[nt][0] * inv0, accO[nt][1] * inv0);
            *(float2*)&o1[c] = make_float2(accO[nt][2] * inv1, accO[nt][3] * inv1);
        }
    }
}

// ---------------- launch ------------------------------------------------------
static float* dev_ptr(const void* sym)
{
    void* p = nullptr;
    cudaGetSymbolAddress(&p, sym);
    return (float*)p;
}

extern "C" void kernel_launch(void* const* d_in, const int* in_sizes, int n_in,
                              void* d_out, int out_size)
{
    (void)in_sizes; (void)n_in; (void)out_size;
    const float* x   = (const float*)d_in[0];
    const float* wq  = (const float*)d_in[1];
    const float* wk  = (const float*)d_in[2];
    const float* wv  = (const float*)d_in[3];
    const float* wo  = (const float*)d_in[4];
    const float* bo  = (const float*)d_in[5];
    const float* w1  = (const float*)d_in[6];
    const float* b1  = (const float*)d_in[7];
    const float* w2  = (const float*)d_in[8];
    const float* b2  = (const float*)d_in[9];
    const float* g1  = (const float*)d_in[10];
    const float* be1 = (const float*)d_in[11];
    const float* g2  = (const float*)d_in[12];
    const float* be2 = (const float*)d_in[13];
    float* out = (float*)d_out;

    float* h    = dev_ptr(g_h);
    float* qb   = dev_ptr(g_q);
    float* kb   = dev_ptr(g_k);
    float* vb   = dev_ptr(g_v);
    float* ctx  = dev_ptr(g_ctx);
    float* x1   = dev_ptr(g_x1);
    float* ff   = dev_ptr(g_ff);
    float* wqT  = dev_ptr(g_wqT);
    float* wkT  = dev_ptr(g_wkT);
    float* wvT  = dev_ptr(g_wvT);
    float* woT  = dev_ptr(g_woT);
    float* w1T  = dev_ptr(g_w1T);
    float* w2T  = dev_ptr(g_w2T);

    cudaFuncSetAttribute(attn_mma_kernel, cudaFuncAttributeMaxDynamicSharedMemorySize, ATTN_SMEM);
    cudaFuncSetAttribute(qkv_gemm_kernel,
                         cudaFuncAttributeMaxDynamicSharedMemorySize, GEMM_SMEM);
    cudaFuncSetAttribute(tf32_gemm_kernel<false, true, true>,
                         cudaFuncAttributeMaxDynamicSharedMemorySize, GEMM_SMEM);
    cudaFuncSetAttribute(tf32_gemm_kernel<true, true, false>,
                         cudaFuncAttributeMaxDynamicSharedMemorySize, GEMM_SMEM);

    // transpose all weights
    transpose4_kernel<<<dim3(12, 12, 4), dim3(32, 8)>>>(wq, wk, wv, wo,
                                                        wqT, wkT, wvT, woT);
    transpose_kernel<<<dim3(FFDIM / 32, DIM / 32), dim3(32, 8)>>>(w1, w1T, DIM, FFDIM);
    transpose_kernel<<<dim3(DIM / 32, FFDIM / 32), dim3(32, 8)>>>(w2, w2T, FFDIM, DIM);

    // LN1
    ln_kernel<<<NTOK / 8, 256>>>(x, g1, be1, h);
    // fused QKV projections
    qkv_gemm_kernel<<<dim3(NTOK / 128, 9), 256, GEMM_SMEM>>>(h, wqT, wkT, wvT, qb, kb, vb);
    // attention (tf32 mma)
    attn_mma_kernel<<<dim3(SEQ / 64, NHEAD, BATCH), 128, ATTN_SMEM>>>(qb, kb, vb, ctx);
    // output projection + residual
    tf32_gemm_kernel<false, true, true><<<dim3(NTOK / 128, 3), 256, GEMM_SMEM>>>(ctx, woT, bo, x, x1, DIM, DIM);
    // LN2
    ln_kernel<<<NTOK / 8, 256>>>(x1, g2, be2, h);
    // FFN
    tf32_gemm_kernel<true, true, false><<<dim3(NTOK / 128, 12), 256, GEMM_SMEM>>>(h, w1T, b1, nullptr, ff, DIM, FFDIM);
    tf32_gemm_kernel<false, true, true><<<dim3(NTOK / 128, 3), 256, GEMM_SMEM>>>(ff, w2T, b2, x1, out, FFDIM, DIM);
}

// round 9
// speedup vs baseline: 1.2896x; 1.0534x over previous
#include <cuda_runtime.h>
#include <cuda_bf16.h>
#include <cstdint>
#include <math.h>

// Problem dims
#define BATCH 64
#define SEQ   256
#define DIM   384
#define NHEAD 6
#define HDIM  64
#define NTOK  (BATCH * SEQ)      // 16384
#define FFDIM (4 * DIM)          // 1536

// ---------------- scratch (static device globals; no allocation) -------------
__device__ float g_h  [NTOK * DIM];
__device__ float g_q  [NTOK * DIM];
__device__ float g_k  [NTOK * DIM];
__device__ float g_v  [NTOK * DIM];
__device__ float g_ctx[NTOK * DIM];
__device__ float g_x1 [NTOK * DIM];
__device__ float g_ff [NTOK * FFDIM];
// transposed weights [M][K]
__device__ float g_wqT[DIM * DIM];
__device__ float g_wkT[DIM * DIM];
__device__ float g_wvT[DIM * DIM];
__device__ float g_woT[DIM * DIM];
__device__ float g_w1T[DIM * FFDIM];
__device__ float g_w2T[FFDIM * DIM];

// ---------------- PTX helpers -------------------------------------------------
__device__ __forceinline__ uint32_t smem_u32(const void* p) {
    uint32_t a;
    asm("{ .reg .u64 t; cvta.to.shared.u64 t, %1; cvt.u32.u64 %0, t; }"
        : "=r"(a) : "l"(p));
    return a;
}
__device__ __forceinline__ void cp_async16(uint32_t dst, const void* src) {
    asm volatile("cp.async.cg.shared.global [%0], [%1], 16;" :: "r"(dst), "l"(src));
}
__device__ __forceinline__ void cp_commit() {
    asm volatile("cp.async.commit_group;" ::: "memory");
}
template<int N> __device__ __forceinline__ void cp_wait() {
    asm volatile("cp.async.wait_group %0;" :: "n"(N) : "memory");
}
__device__ __forceinline__ void mma_tf32(float* c, const uint32_t* a, const uint32_t* b) {
    asm volatile(
        "mma.sync.aligned.m16n8k8.row.col.f32.tf32.tf32.f32 "
        "{%0,%1,%2,%3}, {%4,%5,%6,%7}, {%8,%9}, {%0,%1,%2,%3};"
        : "+f"(c[0]), "+f"(c[1]), "+f"(c[2]), "+f"(c[3])
        : "r"(a[0]), "r"(a[1]), "r"(a[2]), "r"(a[3]), "r"(b[0]), "r"(b[1]));
}
__device__ __forceinline__ void ldsm_x4(uint32_t& r0, uint32_t& r1, uint32_t& r2,
                                        uint32_t& r3, uint32_t addr) {
    asm volatile("ldmatrix.sync.aligned.m8n8.x4.shared.b16 {%0,%1,%2,%3}, [%4];"
                 : "=r"(r0), "=r"(r1), "=r"(r2), "=r"(r3) : "r"(addr));
}
__device__ __forceinline__ uint32_t lds32(uint32_t addr) {
    uint32_t v;
    asm volatile("ld.shared.b32 %0, [%1];" : "=r"(v) : "r"(addr));
    return v;
}

// ================= tf32 mma.sync GEMM, cp.async 3-stage + ldmatrix ===========
// Single __syncthreads per k-tile: order = wait -> barrier -> issue copy -> MMA.
#define BK       32
#define STRD     144                      // bytes per smem row (36 floats)
#define SA_BYTES (128 * STRD)             // 18432
#define SB_BYTES (128 * STRD)             // 18432
#define STAGE_BYTES (SA_BYTES + SB_BYTES) // 36864
#define STAGES   3
#define GEMM_SMEM (STAGES * STAGE_BYTES)  // 110592

template<bool RELU, bool BIAS, bool RESID>
__device__ __forceinline__ void gemm_body(
    uint32_t sb,
    const float* __restrict__ A, const float* __restrict__ WT,
    const float* __restrict__ bias, const float* __restrict__ resid,
    float* __restrict__ C, int K, int M, int row0, int col0)
{
    const int tid  = threadIdx.x;
    const int wid  = tid >> 5;
    const int lane = tid & 31;
    const int warpM = wid & 1;
    const int warpN = wid >> 1;
    const int g = lane >> 2, t = lane & 3;

    const int laneRowA = ((lane >> 3) & 1) * 8 + (lane & 7);
    const int laneKA   = (lane >> 4) * 16;
    const int laneRowB = (lane >> 4) * 8 + (lane & 7);
    const int laneKB   = ((lane >> 3) & 1) * 16;

    float acc[4][4][4];
#pragma unroll
    for (int mt = 0; mt < 4; mt++)
#pragma unroll
        for (int nt = 0; nt < 4; nt++)
#pragma unroll
            for (int f = 0; f < 4; f++) acc[mt][nt][f] = 0.f;

    const int KT = K >> 5;

    auto copy_stage = [&](int kt, int st) {
        const int k0 = kt << 5;
        const uint32_t abase = sb + st * STAGE_BYTES;
        const uint32_t bbase = abase + SA_BYTES;
#pragma unroll
        for (int i = 0; i < 4; i++) {
            int c = tid + (i << 8);
            int r = c >> 3, k4 = c & 7;
            cp_async16(abase + r * STRD + (k4 << 4),
                       &A[(size_t)(row0 + r) * K + k0 + (k4 << 2)]);
        }
#pragma unroll
        for (int i = 0; i < 4; i++) {
            int c = tid + (i << 8);
            int n = c >> 3, k4 = c & 7;
            cp_async16(bbase + n * STRD + (k4 << 4),
                       &WT[(size_t)(col0 + n) * K + k0 + (k4 << 2)]);
        }
    };

    copy_stage(0, 0); cp_commit();
    copy_stage(1, 1); cp_commit();

    for (int kt = 0; kt < KT; kt++) {
        const int st = kt % STAGES;
        cp_wait<1>();          // group kt resident (group kt+1 may be pending)
        __syncthreads();       // all warps done reading stage written next
        if (kt + 2 < KT) copy_stage(kt + 2, (kt + 2) % STAGES);
        cp_commit();

        const uint32_t aB = sb + st * STAGE_BYTES
                          + (warpM * 64 + laneRowA) * STRD + laneKA;
        const uint32_t bB = sb + st * STAGE_BYTES + SA_BYTES
                          + (warpN * 32 + laneRowB) * STRD + laneKB;
#pragma unroll
        for (int kc = 0; kc < 4; kc++) {
            uint32_t a_[4][4], b_[4][2];
#pragma unroll
            for (int mt = 0; mt < 4; mt++)
                ldsm_x4(a_[mt][0], a_[mt][1], a_[mt][2], a_[mt][3],
                        aB + mt * 16 * STRD + (kc << 5));
            ldsm_x4(b_[0][0], b_[0][1], b_[1][0], b_[1][1], bB + (kc << 5));
            ldsm_x4(b_[2][0], b_[2][1], b_[3][0], b_[3][1],
                    bB + 16 * STRD + (kc << 5));
#pragma unroll
            for (int mt = 0; mt < 4; mt++)
#pragma unroll
                for (int nt = 0; nt < 4; nt++)
                    mma_tf32(acc[mt][nt], a_[mt], b_[nt]);
        }
    }

#pragma unroll
    for (int mt = 0; mt < 4; mt++) {
        int r_lo = row0 + warpM * 64 + mt * 16 + g;
        int r_hi = r_lo + 8;
#pragma unroll
        for (int nt = 0; nt < 4; nt++) {
            int col = col0 + warpN * 32 + nt * 8 + (t << 1);
            float2 v0 = make_float2(acc[mt][nt][0], acc[mt][nt][1]);
            float2 v1 = make_float2(acc[mt][nt][2], acc[mt][nt][3]);
            if (BIAS) {
                float2 bv = *(const float2*)&bias[col];
                v0.x += bv.x; v0.y += bv.y;
                v1.x += bv.x; v1.y += bv.y;
            }
            if (RESID) {
                float2 q0 = *(const float2*)&resid[(size_t)r_lo * M + col];
                float2 q1 = *(const float2*)&resid[(size_t)r_hi * M + col];
                v0.x += q0.x; v0.y += q0.y;
                v1.x += q1.x; v1.y += q1.y;
            }
            if (RELU) {
                v0.x = fmaxf(v0.x, 0.f); v0.y = fmaxf(v0.y, 0.f);
                v1.x = fmaxf(v1.x, 0.f); v1.y = fmaxf(v1.y, 0.f);
            }
            *(float2*)&C[(size_t)r_lo * M + col] = v0;
            *(float2*)&C[(size_t)r_hi * M + col] = v1;
        }
    }
}

template<bool RELU, bool BIAS, bool RESID>
__global__ void __launch_bounds__(256, 2)
tf32_gemm_kernel(const float* __restrict__ A, const float* __restrict__ WT,
                 const float* __restrict__ bias, const float* __restrict__ resid,
                 float* __restrict__ C, int K, int M)
{
    extern __shared__ char smem[];
    gemm_body<RELU, BIAS, RESID>(smem_u32(smem), A, WT, bias, resid, C, K, M,
                                 blockIdx.x * 128, blockIdx.y * 128);
}

__global__ void __launch_bounds__(256, 2)
qkv_gemm_kernel(const float* __restrict__ A,
                const float* __restrict__ wqT, const float* __restrict__ wkT,
                const float* __restrict__ wvT,
                float* __restrict__ q, float* __restrict__ k, float* __restrict__ v)
{
    extern __shared__ char smem[];
    int y = blockIdx.y;
    int sel = y / 3;
    int col0 = (y - sel * 3) * 128;
    const float* WT = (sel == 0) ? wqT : (sel == 1) ? wkT : wvT;
    float* C = (sel == 0) ? q : (sel == 1) ? k : v;
    gemm_body<false, false, false>(smem_u32(smem), A, WT, nullptr, nullptr, C,
                                   DIM, DIM, blockIdx.x * 128, col0);
}

// ---------------- merged weight transpose (1 launch, 1728 tiles) --------------
__global__ void transpose_all_kernel(
    const float* __restrict__ wq, const float* __restrict__ wk,
    const float* __restrict__ wv, const float* __restrict__ wo,
    const float* __restrict__ w1, const float* __restrict__ w2,
    float* __restrict__ wqT, float* __restrict__ wkT,
    float* __restrict__ wvT, float* __restrict__ woT,
    float* __restrict__ w1T, float* __restrict__ w2T)
{
    __shared__ float tbuf[32][33];
    int id = blockIdx.x;
    const float* in; float* out; int R, C, bx, by;
    if (id < 576) {
        int m = id / 144, r = id - m * 144;
        switch (m) {
            case 0: in = wq; out = wqT; break;
            case 1: in = wk; out = wkT; break;
            case 2: in = wv; out = wvT; break;
            default: in = wo; out = woT; break;
        }
        R = DIM; C = DIM; bx = (r % 12) * 32; by = (r / 12) * 32;
    } else if (id < 1152) {
        int r = id - 576;
        in = w1; out = w1T; R = DIM; C = FFDIM;
        bx = (r % 48) * 32; by = (r / 48) * 32;
    } else {
        int r = id - 1152;
        in = w2; out = w2T; R = FFDIM; C = DIM;
        bx = (r % 12) * 32; by = (r / 12) * 32;
    }
#pragma unroll
    for (int i = 0; i < 32; i += 8)
        tbuf[threadIdx.y + i][threadIdx.x] =
            in[(size_t)(by + threadIdx.y + i) * C + bx + threadIdx.x];
    __syncthreads();
#pragma unroll
    for (int i = 0; i < 32; i += 8)
        out[(size_t)(bx + threadIdx.y + i) * R + by + threadIdx.x] =
            tbuf[threadIdx.x][threadIdx.y + i];
}

// ---------------- LayerNorm ----------------------------------------------------
__global__ void ln_kernel(const float* __restrict__ x,
                          const float* __restrict__ g,
                          const float* __restrict__ be,
                          float* __restrict__ out)
{
    int warp = (blockIdx.x * blockDim.x + threadIdx.x) >> 5;
    int lane = threadIdx.x & 31;
    if (warp >= NTOK) return;
    const float* row = x + (size_t)warp * DIM;
    float v[12];
    float s = 0.f, ss = 0.f;
#pragma unroll
    for (int i = 0; i < 12; i++) {
        v[i] = row[lane + 32 * i];
        s  += v[i];
        ss += v[i] * v[i];
    }
#pragma unroll
    for (int o = 16; o; o >>= 1) {
        s  += __shfl_xor_sync(0xffffffffu, s, o);
        ss += __shfl_xor_sync(0xffffffffu, ss, o);
    }
    float mean = s * (1.0f / DIM);
    float var  = ss * (1.0f / DIM) - mean * mean;
    float rstd = rsqrtf(var + 1e-5f);
    float* orow = out + (size_t)warp * DIM;
#pragma unroll
    for (int i = 0; i < 12; i++) {
        int c = lane + 32 * i;
        orow[c] = (v[i] - mean) * rstd * g[c] + be[c];
    }
}

// ---------------- Tensor-core causal flash attention --------------------------
// 64 queries/CTA, 128 threads (4 warps x 16 q-rows). Register softmax:
// row stats via shfl over the 4 lanes sharing g; P stays in registers and is
// re-shaped to A-fragments with shuffles. One __syncthreads per k-tile.
// smem: Q[64][68] + 2 stages x (K[64][68], V[64][68]) = 87040 B.
#define AT_RS    68
#define AT_RB    (AT_RS * 4)               // 272
#define AT_TILE  (64 * AT_RB)              // 17408
#define AT_QOFF  0
#define AT_KVOFF AT_TILE
#define AT_STAGE (2 * AT_TILE)
#define ATTN_SMEM (AT_TILE + 2 * AT_STAGE) // 87040

__global__ void __launch_bounds__(128, 2)
attn_mma_kernel(const float* __restrict__ q, const float* __restrict__ k,
                const float* __restrict__ v, float* __restrict__ ctx)
{
    extern __shared__ float sm[];
    const uint32_t sb = smem_u32(sm);

    const int qt = blockIdx.x;
    const int h  = blockIdx.y;
    const int b  = blockIdx.z;
    const int tid = threadIdx.x;
    const int wid = tid >> 5;
    const int lane = tid & 31;
    const int g = lane >> 2, t = lane & 3;
    const int w16 = wid * 16;

    const float* qbase = q + (size_t)b * SEQ * DIM + h * HDIM;
    const float* kbase = k + (size_t)b * SEQ * DIM + h * HDIM;
    const float* vbase = v + (size_t)b * SEQ * DIM + h * HDIM;

#pragma unroll
    for (int i = 0; i < 8; i++) {
        int f = tid + (i << 7);
        int r = f >> 4, d4 = (f & 15) << 2;
        cp_async16(sb + AT_QOFF + r * AT_RB + (d4 << 2),
                   &qbase[(size_t)(qt * 64 + r) * DIM + d4]);
    }
    auto copy_kv = [&](int kt, int st) {
        const uint32_t kdst = sb + AT_KVOFF + st * AT_STAGE;
        const uint32_t vdst = kdst + AT_TILE;
#pragma unroll
        for (int i = 0; i < 8; i++) {
            int f = tid + (i << 7);
            int r = f >> 4, d4 = (f & 15) << 2;
            cp_async16(kdst + r * AT_RB + (d4 << 2),
                       &kbase[(size_t)(kt * 64 + r) * DIM + d4]);
        }
#pragma unroll
        for (int i = 0; i < 8; i++) {
            int f = tid + (i << 7);
            int r = f >> 4, d4 = (f & 15) << 2;
            cp_async16(vdst + r * AT_RB + (d4 << 2),
                       &vbase[(size_t)(kt * 64 + r) * DIM + d4]);
        }
    };

    copy_kv(0, 0);
    cp_commit();

    float m0 = -1e30f, m1 = -1e30f, l0 = 0.f, l1 = 0.f;
    float accO[8][4];
#pragma unroll
    for (int nt = 0; nt < 8; nt++)
#pragma unroll
        for (int f = 0; f < 4; f++) accO[nt][f] = 0.f;

    const int gq0 = qt * 64 + w16 + g;
    const int gq1 = gq0 + 8;
    const int src_lo = (lane & ~3) | (t >> 1);
    const int src_hi = src_lo + 2;

    const int KT = qt + 1;
    for (int kt = 0; kt < KT; kt++) {
        const int st = kt & 1;
        cp_wait<0>();
        __syncthreads();
        if (kt + 1 < KT) copy_kv(kt + 1, st ^ 1);
        cp_commit();

        // ---- S = Q @ K^T ----
        float accS[8][4];
#pragma unroll
        for (int nt = 0; nt < 8; nt++)
#pragma unroll
            for (int f = 0; f < 4; f++) accS[nt][f] = 0.f;

        const uint32_t aQ = sb + AT_QOFF + (w16 + g) * AT_RB + (t << 2);
        const uint32_t bK = sb + AT_KVOFF + st * AT_STAGE + g * AT_RB + (t << 2);
#pragma unroll
        for (int kc = 0; kc < 8; kc++) {
            uint32_t a_[4];
            a_[0] = lds32(aQ + (kc << 5));
            a_[1] = lds32(aQ + 8 * AT_RB + (kc << 5));
            a_[2] = lds32(aQ + (kc << 5) + 16);
            a_[3] = lds32(aQ + 8 * AT_RB + (kc << 5) + 16);
#pragma unroll
            for (int nt = 0; nt < 8; nt++) {
                uint32_t b_[2];
                uint32_t ba = bK + nt * 8 * AT_RB + (kc << 5);
                b_[0] = lds32(ba);
                b_[1] = lds32(ba + 16);
                mma_tf32(accS[nt], a_, b_);
            }
        }

        // ---- mask + scale (in registers) ----
#pragma unroll
        for (int nt = 0; nt < 8; nt++) {
            int gk = kt * 64 + nt * 8 + (t << 1);
            accS[nt][0] = (gk     > gq0) ? -1e30f : accS[nt][0] * 0.125f;
            accS[nt][1] = (gk + 1 > gq0) ? -1e30f : accS[nt][1] * 0.125f;
            accS[nt][2] = (gk     > gq1) ? -1e30f : accS[nt][2] * 0.125f;
            accS[nt][3] = (gk + 1 > gq1) ? -1e30f : accS[nt][3] * 0.125f;
        }

        // ---- register softmax (row spread over 4 lanes sharing g) ----
        float pm0 = -1e30f, pm1 = -1e30f;
#pragma unroll
        for (int nt = 0; nt < 8; nt++) {
            pm0 = fmaxf(pm0, fmaxf(accS[nt][0], accS[nt][1]));
            pm1 = fmaxf(pm1, fmaxf(accS[nt][2], accS[nt][3]));
        }
        pm0 = fmaxf(pm0, __shfl_xor_sync(0xffffffffu, pm0, 1));
        pm0 = fmaxf(pm0, __shfl_xor_sync(0xffffffffu, pm0, 2));
        pm1 = fmaxf(pm1, __shfl_xor_sync(0xffffffffu, pm1, 1));
        pm1 = fmaxf(pm1, __shfl_xor_sync(0xffffffffu, pm1, 2));
        float mn0 = fmaxf(m0, pm0), mn1 = fmaxf(m1, pm1);
        float al0 = __expf(m0 - mn0), al1 = __expf(m1 - mn1);
        m0 = mn0; m1 = mn1;
        float sum0 = 0.f, sum1 = 0.f;
#pragma unroll
        for (int nt = 0; nt < 8; nt++) {
            accS[nt][0] = __expf(accS[nt][0] - mn0);
            accS[nt][1] = __expf(accS[nt][1] - mn0);
            accS[nt][2] = __expf(accS[nt][2] - mn1);
            accS[nt][3] = __expf(accS[nt][3] - mn1);
            sum0 += accS[nt][0] + accS[nt][1];
            sum1 += accS[nt][2] + accS[nt][3];
        }
        sum0 += __shfl_xor_sync(0xffffffffu, sum0, 1);
        sum0 += __shfl_xor_sync(0xffffffffu, sum0, 2);
        sum1 += __shfl_xor_sync(0xffffffffu, sum1, 1);
        sum1 += __shfl_xor_sync(0xffffffffu, sum1, 2);
        l0 = l0 * al0 + sum0;
        l1 = l1 * al1 + sum1;

        // ---- O = O*alpha + P @ V ----
#pragma unroll
        for (int nt = 0; nt < 8; nt++) {
            accO[nt][0] *= al0; accO[nt][1] *= al0;
            accO[nt][2] *= al1; accO[nt][3] *= al1;
        }
        const uint32_t bV = sb + AT_KVOFF + st * AT_STAGE + AT_TILE
                          + t * AT_RB + (g << 2);
#pragma unroll
        for (int kc = 0; kc < 8; kc++) {
            // build P A-fragment via shuffles:
            // a0 = P[r0][8kc+t], a1 = P[r1][8kc+t], a2 = P[r0][8kc+t+4], a3 = P[r1][8kc+t+4]
            float x0 = __shfl_sync(0xffffffffu, accS[kc][0], src_lo);
            float x1 = __shfl_sync(0xffffffffu, accS[kc][1], src_lo);
            float y0 = __shfl_sync(0xffffffffu, accS[kc][0], src_hi);
            float y1 = __shfl_sync(0xffffffffu, accS[kc][1], src_hi);
            float z0 = __shfl_sync(0xffffffffu, accS[kc][2], src_lo);
            float z1 = __shfl_sync(0xffffffffu, accS[kc][3], src_lo);
            float u0 = __shfl_sync(0xffffffffu, accS[kc][2], src_hi);
            float u1 = __shfl_sync(0xffffffffu, accS[kc][3], src_hi);
            uint32_t a_[4];
            a_[0] = __float_as_uint((t & 1) ? x1 : x0);
            a_[1] = __float_as_uint((t & 1) ? z1 : z0);
            a_[2] = __float_as_uint((t & 1) ? y1 : y0);
            a_[3] = __float_as_uint((t & 1) ? u1 : u0);
#pragma unroll
            for (int nt = 0; nt < 8; nt++) {
                uint32_t b_[2];
                uint32_t ba = bV + kc * 8 * AT_RB + (nt << 5);
                b_[0] = lds32(ba);
                b_[1] = lds32(ba + 4 * AT_RB);
                mma_tf32(accO[nt], a_, b_);
            }
        }
    }

    // ---- write ctx = O / l ----
    {
        const int r0 = w16 + g, r1 = r0 + 8;
        float inv0 = 1.0f / l0;
        float inv1 = 1.0f / l1;
        float* obase = ctx + (size_t)b * SEQ * DIM + h * HDIM;
        float* o0 = &obase[(size_t)(qt * 64 + r0) * DIM];
        float* o1 = &obase[(size_t)(qt * 64 + r1) * DIM];
#pragma unroll
        for (int nt = 0; nt < 8; nt++) {
            int c = nt * 8 + (t << 1);
            *(float2*)&o0[c] = make_float2(accO[nt][0] * inv0, accO[nt][1] * inv0);
            *(float2*)&o1[c] = make_float2(accO[nt][2] * inv1, accO[nt][3] * inv1);
        }
    }
}

// ---------------- launch ------------------------------------------------------
static float* dev_ptr(const void* sym)
{
    void* p = nullptr;
    cudaGetSymbolAddress(&p, sym);
    return (float*)p;
}

extern "C" void kernel_launch(void* const* d_in, const int* in_sizes, int n_in,
                              void* d_out, int out_size)
{
    (void)in_sizes; (void)n_in; (void)out_size;
    const float* x   = (const float*)d_in[0];
    const float* wq  = (const float*)d_in[1];
    const float* wk  = (const float*)d_in[2];
    const float* wv  = (const float*)d_in[3];
    const float* wo  = (const float*)d_in[4];
    const float* bo  = (const float*)d_in[5];
    const float* w1  = (const float*)d_in[6];
    const float* b1  = (const float*)d_in[7];
    const float* w2  = (const float*)d_in[8];
    const float* b2  = (const float*)d_in[9];
    const float* g1  = (const float*)d_in[10];
    const float* be1 = (const float*)d_in[11];
    const float* g2  = (const float*)d_in[12];
    const float* be2 = (const float*)d_in[13];
    float* out = (float*)d_out;

    float* h    = dev_ptr(g_h);
    float* qb   = dev_ptr(g_q);
    float* kb   = dev_ptr(g_k);
    float* vb   = dev_ptr(g_v);
    float* ctx  = dev_ptr(g_ctx);
    float* x1   = dev_ptr(g_x1);
    float* ff   = dev_ptr(g_ff);
    float* wqT  = dev_ptr(g_wqT);
    float* wkT  = dev_ptr(g_wkT);
    float* wvT  = dev_ptr(g_wvT);
    float* woT  = dev_ptr(g_woT);
    float* w1T  = dev_ptr(g_w1T);
    float* w2T  = dev_ptr(g_w2T);

    cudaFuncSetAttribute(attn_mma_kernel, cudaFuncAttributeMaxDynamicSharedMemorySize, ATTN_SMEM);
    cudaFuncSetAttribute(qkv_gemm_kernel,
                         cudaFuncAttributeMaxDynamicSharedMemorySize, GEMM_SMEM);
    cudaFuncSetAttribute(tf32_gemm_kernel<false, true, true>,
                         cudaFuncAttributeMaxDynamicSharedMemorySize, GEMM_SMEM);
    cudaFuncSetAttribute(tf32_gemm_kernel<true, true, false>,
                         cudaFuncAttributeMaxDynamicSharedMemorySize, GEMM_SMEM);

    // all weight transposes in one launch
    transpose_all_kernel<<<1728, dim3(32, 8)>>>(wq, wk, wv, wo, w1, w2,
                                                wqT, wkT, wvT, woT, w1T, w2T);
    // LN1
    ln_kernel<<<NTOK / 8, 256>>>(x, g1, be1, h);
    // fused QKV projections
    qkv_gemm_kernel<<<dim3(NTOK / 128, 9), 256, GEMM_SMEM>>>(h, wqT, wkT, wvT, qb, kb, vb);
    // attention (tf32 mma, register softmax)
    attn_mma_kernel<<<dim3(SEQ / 64, NHEAD, BATCH), 128, ATTN_SMEM>>>(qb, kb, vb, ctx);
    // output projection + residual
    tf32_gemm_kernel<false, true, true><<<dim3(NTOK / 128, 3), 256, GEMM_SMEM>>>(ctx, woT, bo, x, x1, DIM, DIM);
    // LN2
    ln_kernel<<<NTOK / 8, 256>>>(x1, g2, be2, h);
    // FFN
    tf32_gemm_kernel<true, true, false><<<dim3(NTOK / 128, 12), 256, GEMM_SMEM>>>(h, w1T, b1, nullptr, ff, DIM, FFDIM);
    tf32_gemm_kernel<false, true, true><<<dim3(NTOK / 128, 3), 256, GEMM_SMEM>>>(ff, w2T, b2, x1, out, FFDIM, DIM);
}

// round 10
// speedup vs baseline: 1.3088x; 1.0149x over previous
#include <cuda_runtime.h>
#include <cuda_bf16.h>
#include <cstdint>
#include <math.h>

// Problem dims
#define BATCH 64
#define SEQ   256
#define DIM   384
#define NHEAD 6
#define HDIM  64
#define NTOK  (BATCH * SEQ)      // 16384
#define FFDIM (4 * DIM)          // 1536

// ---------------- scratch (static device globals; no allocation) -------------
__device__ float g_h  [NTOK * DIM];
__device__ float g_q  [NTOK * DIM];
__device__ float g_k  [NTOK * DIM];
__device__ float g_v  [NTOK * DIM];
__device__ float g_ctx[NTOK * DIM];
__device__ float g_x1 [NTOK * DIM];
__device__ float g_ff [NTOK * FFDIM];
// transposed weights [M][K]
__device__ float g_wqT[DIM * DIM];
__device__ float g_wkT[DIM * DIM];
__device__ float g_wvT[DIM * DIM];
__device__ float g_woT[DIM * DIM];
__device__ float g_w1T[DIM * FFDIM];
__device__ float g_w2T[FFDIM * DIM];

// ---------------- PTX helpers -------------------------------------------------
__device__ __forceinline__ uint32_t smem_u32(const void* p) {
    uint32_t a;
    asm("{ .reg .u64 t; cvta.to.shared.u64 t, %1; cvt.u32.u64 %0, t; }"
        : "=r"(a) : "l"(p));
    return a;
}
__device__ __forceinline__ void cp_async16(uint32_t dst, const void* src) {
    asm volatile("cp.async.cg.shared.global [%0], [%1], 16;" :: "r"(dst), "l"(src));
}
__device__ __forceinline__ void cp_commit() {
    asm volatile("cp.async.commit_group;" ::: "memory");
}
template<int N> __device__ __forceinline__ void cp_wait() {
    asm volatile("cp.async.wait_group %0;" :: "n"(N) : "memory");
}
__device__ __forceinline__ void mma_tf32(float* c, const uint32_t* a, const uint32_t* b) {
    asm volatile(
        "mma.sync.aligned.m16n8k8.row.col.f32.tf32.tf32.f32 "
        "{%0,%1,%2,%3}, {%4,%5,%6,%7}, {%8,%9}, {%0,%1,%2,%3};"
        : "+f"(c[0]), "+f"(c[1]), "+f"(c[2]), "+f"(c[3])
        : "r"(a[0]), "r"(a[1]), "r"(a[2]), "r"(a[3]), "r"(b[0]), "r"(b[1]));
}
__device__ __forceinline__ void ldsm_x4(uint32_t& r0, uint32_t& r1, uint32_t& r2,
                                        uint32_t& r3, uint32_t addr) {
    asm volatile("ldmatrix.sync.aligned.m8n8.x4.shared.b16 {%0,%1,%2,%3}, [%4];"
                 : "=r"(r0), "=r"(r1), "=r"(r2), "=r"(r3) : "r"(addr));
}
__device__ __forceinline__ uint32_t lds32(uint32_t addr) {
    uint32_t v;
    asm volatile("ld.shared.b32 %0, [%1];" : "=r"(v) : "r"(addr));
    return v;
}

// ================= tf32 mma.sync GEMM, cp.async 3-stage + ldmatrix ===========
#define BK       32
#define STRD     144                      // bytes per smem row (36 floats)
#define SA_BYTES (128 * STRD)             // 18432
#define SB_BYTES (128 * STRD)             // 18432
#define STAGE_BYTES (SA_BYTES + SB_BYTES) // 36864
#define STAGES   3
#define GEMM_SMEM (STAGES * STAGE_BYTES)  // 110592

template<bool RELU, bool BIAS, bool RESID>
__device__ __forceinline__ void gemm_body(
    uint32_t sb,
    const float* __restrict__ A, const float* __restrict__ WT,
    const float* __restrict__ bias, const float* __restrict__ resid,
    float* __restrict__ C, int K, int M, int row0, int col0)
{
    const int tid  = threadIdx.x;
    const int wid  = tid >> 5;
    const int lane = tid & 31;
    const int warpM = wid & 1;
    const int warpN = wid >> 1;
    const int g = lane >> 2, t = lane & 3;

    const int laneRowA = ((lane >> 3) & 1) * 8 + (lane & 7);
    const int laneKA   = (lane >> 4) * 16;
    const int laneRowB = (lane >> 4) * 8 + (lane & 7);
    const int laneKB   = ((lane >> 3) & 1) * 16;

    float acc[4][4][4];
#pragma unroll
    for (int mt = 0; mt < 4; mt++)
#pragma unroll
        for (int nt = 0; nt < 4; nt++)
#pragma unroll
            for (int f = 0; f < 4; f++) acc[mt][nt][f] = 0.f;

    const int KT = K >> 5;

    auto copy_stage = [&](int kt, int st) {
        const int k0 = kt << 5;
        const uint32_t abase = sb + st * STAGE_BYTES;
        const uint32_t bbase = abase + SA_BYTES;
#pragma unroll
        for (int i = 0; i < 4; i++) {
            int c = tid + (i << 8);
            int r = c >> 3, k4 = c & 7;
            cp_async16(abase + r * STRD + (k4 << 4),
                       &A[(size_t)(row0 + r) * K + k0 + (k4 << 2)]);
        }
#pragma unroll
        for (int i = 0; i < 4; i++) {
            int c = tid + (i << 8);
            int n = c >> 3, k4 = c & 7;
            cp_async16(bbase + n * STRD + (k4 << 4),
                       &WT[(size_t)(col0 + n) * K + k0 + (k4 << 2)]);
        }
    };

    copy_stage(0, 0); cp_commit();
    copy_stage(1, 1); cp_commit();

    for (int kt = 0; kt < KT; kt++) {
        const int st = kt % STAGES;
        cp_wait<1>();
        __syncthreads();
        if (kt + 2 < KT) copy_stage(kt + 2, (kt + 2) % STAGES);
        cp_commit();

        const uint32_t aB = sb + st * STAGE_BYTES
                          + (warpM * 64 + laneRowA) * STRD + laneKA;
        const uint32_t bB = sb + st * STAGE_BYTES + SA_BYTES
                          + (warpN * 32 + laneRowB) * STRD + laneKB;
#pragma unroll
        for (int kc = 0; kc < 4; kc++) {
            uint32_t a_[4][4], b_[4][2];
#pragma unroll
            for (int mt = 0; mt < 4; mt++)
                ldsm_x4(a_[mt][0], a_[mt][1], a_[mt][2], a_[mt][3],
                        aB + mt * 16 * STRD + (kc << 5));
            ldsm_x4(b_[0][0], b_[0][1], b_[1][0], b_[1][1], bB + (kc << 5));
            ldsm_x4(b_[2][0], b_[2][1], b_[3][0], b_[3][1],
                    bB + 16 * STRD + (kc << 5));
#pragma unroll
            for (int mt = 0; mt < 4; mt++)
#pragma unroll
                for (int nt = 0; nt < 4; nt++)
                    mma_tf32(acc[mt][nt], a_[mt], b_[nt]);
        }
    }

#pragma unroll
    for (int mt = 0; mt < 4; mt++) {
        int r_lo = row0 + warpM * 64 + mt * 16 + g;
        int r_hi = r_lo + 8;
#pragma unroll
        for (int nt = 0; nt < 4; nt++) {
            int col = col0 + warpN * 32 + nt * 8 + (t << 1);
            float2 v0 = make_float2(acc[mt][nt][0], acc[mt][nt][1]);
            float2 v1 = make_float2(acc[mt][nt][2], acc[mt][nt][3]);
            if (BIAS) {
                float2 bv = *(const float2*)&bias[col];
                v0.x += bv.x; v0.y += bv.y;
                v1.x += bv.x; v1.y += bv.y;
            }
            if (RESID) {
                float2 q0 = *(const float2*)&resid[(size_t)r_lo * M + col];
                float2 q1 = *(const float2*)&resid[(size_t)r_hi * M + col];
                v0.x += q0.x; v0.y += q0.y;
                v1.x += q1.x; v1.y += q1.y;
            }
            if (RELU) {
                v0.x = fmaxf(v0.x, 0.f); v0.y = fmaxf(v0.y, 0.f);
                v1.x = fmaxf(v1.x, 0.f); v1.y = fmaxf(v1.y, 0.f);
            }
            *(float2*)&C[(size_t)r_lo * M + col] = v0;
            *(float2*)&C[(size_t)r_hi * M + col] = v1;
        }
    }
}

template<bool RELU, bool BIAS, bool RESID>
__global__ void __launch_bounds__(256, 2)
tf32_gemm_kernel(const float* __restrict__ A, const float* __restrict__ WT,
                 const float* __restrict__ bias, const float* __restrict__ resid,
                 float* __restrict__ C, int K, int M)
{
    extern __shared__ char smem[];
    gemm_body<RELU, BIAS, RESID>(smem_u32(smem), A, WT, bias, resid, C, K, M,
                                 blockIdx.x * 128, blockIdx.y * 128);
}

__global__ void __launch_bounds__(256, 2)
qkv_gemm_kernel(const float* __restrict__ A,
                const float* __restrict__ wqT, const float* __restrict__ wkT,
                const float* __restrict__ wvT,
                float* __restrict__ q, float* __restrict__ k, float* __restrict__ v)
{
    extern __shared__ char smem[];
    int y = blockIdx.y;
    int sel = y / 3;
    int col0 = (y - sel * 3) * 128;
    const float* WT = (sel == 0) ? wqT : (sel == 1) ? wkT : wvT;
    float* C = (sel == 0) ? q : (sel == 1) ? k : v;
    gemm_body<false, false, false>(smem_u32(smem), A, WT, nullptr, nullptr, C,
                                   DIM, DIM, blockIdx.x * 128, col0);
}

// ---------------- merged weight transpose (1 launch, 1728 tiles) --------------
__global__ void transpose_all_kernel(
    const float* __restrict__ wq, const float* __restrict__ wk,
    const float* __restrict__ wv, const float* __restrict__ wo,
    const float* __restrict__ w1, const float* __restrict__ w2,
    float* __restrict__ wqT, float* __restrict__ wkT,
    float* __restrict__ wvT, float* __restrict__ woT,
    float* __restrict__ w1T, float* __restrict__ w2T)
{
    __shared__ float tbuf[32][33];
    int id = blockIdx.x;
    const float* in; float* out; int R, C, bx, by;
    if (id < 576) {
        int m = id / 144, r = id - m * 144;
        switch (m) {
            case 0: in = wq; out = wqT; break;
            case 1: in = wk; out = wkT; break;
            case 2: in = wv; out = wvT; break;
            default: in = wo; out = woT; break;
        }
        R = DIM; C = DIM; bx = (r % 12) * 32; by = (r / 12) * 32;
    } else if (id < 1152) {
        int r = id - 576;
        in = w1; out = w1T; R = DIM; C = FFDIM;
        bx = (r % 48) * 32; by = (r / 48) * 32;
    } else {
        int r = id - 1152;
        in = w2; out = w2T; R = FFDIM; C = DIM;
        bx = (r % 12) * 32; by = (r / 12) * 32;
    }
#pragma unroll
    for (int i = 0; i < 32; i += 8)
        tbuf[threadIdx.y + i][threadIdx.x] =
            in[(size_t)(by + threadIdx.y + i) * C + bx + threadIdx.x];
    __syncthreads();
#pragma unroll
    for (int i = 0; i < 32; i += 8)
        out[(size_t)(bx + threadIdx.y + i) * R + by + threadIdx.x] =
            tbuf[threadIdx.x][threadIdx.y + i];
}

// ---------------- LayerNorm ----------------------------------------------------
__global__ void ln_kernel(const float* __restrict__ x,
                          const float* __restrict__ g,
                          const float* __restrict__ be,
                          float* __restrict__ out)
{
    int warp = (blockIdx.x * blockDim.x + threadIdx.x) >> 5;
    int lane = threadIdx.x & 31;
    if (warp >= NTOK) return;
    const float* row = x + (size_t)warp * DIM;
    float v[12];
    float s = 0.f, ss = 0.f;
#pragma unroll
    for (int i = 0; i < 12; i++) {
        v[i] = row[lane + 32 * i];
        s  += v[i];
        ss += v[i] * v[i];
    }
#pragma unroll
    for (int o = 16; o; o >>= 1) {
        s  += __shfl_xor_sync(0xffffffffu, s, o);
        ss += __shfl_xor_sync(0xffffffffu, ss, o);
    }
    float mean = s * (1.0f / DIM);
    float var  = ss * (1.0f / DIM) - mean * mean;
    float rstd = rsqrtf(var + 1e-5f);
    float* orow = out + (size_t)warp * DIM;
#pragma unroll
    for (int i = 0; i < 12; i++) {
        int c = lane + 32 * i;
        orow[c] = (v[i] - mean) * rstd * g[c] + be[c];
    }
}

// ---------------- Tensor-core causal flash attention --------------------------
// 64 queries/CTA, 128 threads. Q A-fragments hoisted into registers (ldmatrix,
// once per CTA); K fetched via ldmatrix (stride 68 = conflict-free, same
// residue as GEMM); V stride 72 floats -> bank 8t+g, bijective (no conflicts).
// Register softmax; P reshaped to A-fragments with shuffles.
#define AT_RS    68
#define AT_RB    (AT_RS * 4)               // 272
#define AT_VRB   (72 * 4)                  // 288
#define AT_QTILE (64 * AT_RB)              // 17408
#define AT_KTILE (64 * AT_RB)              // 17408
#define AT_VTILE (64 * AT_VRB)             // 18432
#define AT_STAGE (AT_KTILE + AT_VTILE)     // 35840
#define AT_KVOFF AT_QTILE
#define ATTN_SMEM (AT_QTILE + 2 * AT_STAGE) // 89088

__global__ void __launch_bounds__(128, 2)
attn_mma_kernel(const float* __restrict__ q, const float* __restrict__ k,
                const float* __restrict__ v, float* __restrict__ ctx)
{
    extern __shared__ float sm[];
    const uint32_t sb = smem_u32(sm);

    const int qt = blockIdx.x;
    const int h  = blockIdx.y;
    const int b  = blockIdx.z;
    const int tid = threadIdx.x;
    const int wid = tid >> 5;
    const int lane = tid & 31;
    const int g = lane >> 2, t = lane & 3;
    const int w16 = wid * 16;

    const int laneRowA = ((lane >> 3) & 1) * 8 + (lane & 7);
    const int laneKA   = (lane >> 4) * 16;
    const int laneRowB = (lane >> 4) * 8 + (lane & 7);
    const int laneKB   = ((lane >> 3) & 1) * 16;

    const float* qbase = q + (size_t)b * SEQ * DIM + h * HDIM;
    const float* kbase = k + (size_t)b * SEQ * DIM + h * HDIM;
    const float* vbase = v + (size_t)b * SEQ * DIM + h * HDIM;

    // Q tile cp.async
#pragma unroll
    for (int i = 0; i < 8; i++) {
        int f = tid + (i << 7);
        int r = f >> 4, d4 = (f & 15) << 2;
        cp_async16(sb + r * AT_RB + (d4 << 2),
                   &qbase[(size_t)(qt * 64 + r) * DIM + d4]);
    }
    auto copy_kv = [&](int kt, int st) {
        const uint32_t kdst = sb + AT_KVOFF + st * AT_STAGE;
        const uint32_t vdst = kdst + AT_KTILE;
#pragma unroll
        for (int i = 0; i < 8; i++) {
            int f = tid + (i << 7);
            int r = f >> 4, d4 = (f & 15) << 2;
            cp_async16(kdst + r * AT_RB + (d4 << 2),
                       &kbase[(size_t)(kt * 64 + r) * DIM + d4]);
        }
#pragma unroll
        for (int i = 0; i < 8; i++) {
            int f = tid + (i << 7);
            int r = f >> 4, d4 = (f & 15) << 2;
            cp_async16(vdst + r * AT_VRB + (d4 << 2),
                       &vbase[(size_t)(kt * 64 + r) * DIM + d4]);
        }
    };

    copy_kv(0, 0);
    cp_commit();
    cp_wait<0>();
    __syncthreads();

    // hoist Q A-fragments (8 kc x 4 regs)
    uint32_t qfrag[8][4];
    {
        const uint32_t aQ = sb + (w16 + laneRowA) * AT_RB + laneKA;
#pragma unroll
        for (int kc = 0; kc < 8; kc++)
            ldsm_x4(qfrag[kc][0], qfrag[kc][1], qfrag[kc][2], qfrag[kc][3],
                    aQ + (kc << 5));
    }

    float m0 = -1e30f, m1 = -1e30f, l0 = 0.f, l1 = 0.f;
    float accO[8][4];
#pragma unroll
    for (int nt = 0; nt < 8; nt++)
#pragma unroll
        for (int f = 0; f < 4; f++) accO[nt][f] = 0.f;

    const int gq0 = qt * 64 + w16 + g;
    const int gq1 = gq0 + 8;
    const int src_lo = (lane & ~3) | (t >> 1);
    const int src_hi = src_lo + 2;

    const int KT = qt + 1;
    for (int kt = 0; kt < KT; kt++) {
        const int st = kt & 1;
        if (kt > 0) {
            cp_wait<0>();
            __syncthreads();
        }
        if (kt + 1 < KT) {
            copy_kv(kt + 1, st ^ 1);
            cp_commit();
        }

        // ---- S = Q @ K^T (K via ldmatrix) ----
        float accS[8][4];
#pragma unroll
        for (int nt = 0; nt < 8; nt++)
#pragma unroll
            for (int f = 0; f < 4; f++) accS[nt][f] = 0.f;

        const uint32_t bK = sb + AT_KVOFF + st * AT_STAGE
                          + laneRowB * AT_RB + laneKB;
#pragma unroll
        for (int kc = 0; kc < 8; kc++) {
            uint32_t b_[8][2];
#pragma unroll
            for (int p = 0; p < 4; p++)
                ldsm_x4(b_[2 * p][0], b_[2 * p][1], b_[2 * p + 1][0], b_[2 * p + 1][1],
                        bK + p * 16 * AT_RB + (kc << 5));
#pragma unroll
            for (int nt = 0; nt < 8; nt++)
                mma_tf32(accS[nt], qfrag[kc], b_[nt]);
        }

        // ---- mask + scale (in registers) ----
#pragma unroll
        for (int nt = 0; nt < 8; nt++) {
            int gk = kt * 64 + nt * 8 + (t << 1);
            accS[nt][0] = (gk     > gq0) ? -1e30f : accS[nt][0] * 0.125f;
            accS[nt][1] = (gk + 1 > gq0) ? -1e30f : accS[nt][1] * 0.125f;
            accS[nt][2] = (gk     > gq1) ? -1e30f : accS[nt][2] * 0.125f;
            accS[nt][3] = (gk + 1 > gq1) ? -1e30f : accS[nt][3] * 0.125f;
        }

        // ---- register softmax ----
        float pm0 = -1e30f, pm1 = -1e30f;
#pragma unroll
        for (int nt = 0; nt < 8; nt++) {
            pm0 = fmaxf(pm0, fmaxf(accS[nt][0], accS[nt][1]));
            pm1 = fmaxf(pm1, fmaxf(accS[nt][2], accS[nt][3]));
        }
        pm0 = fmaxf(pm0, __shfl_xor_sync(0xffffffffu, pm0, 1));
        pm0 = fmaxf(pm0, __shfl_xor_sync(0xffffffffu, pm0, 2));
        pm1 = fmaxf(pm1, __shfl_xor_sync(0xffffffffu, pm1, 1));
        pm1 = fmaxf(pm1, __shfl_xor_sync(0xffffffffu, pm1, 2));
        float mn0 = fmaxf(m0, pm0), mn1 = fmaxf(m1, pm1);
        float al0 = __expf(m0 - mn0), al1 = __expf(m1 - mn1);
        m0 = mn0; m1 = mn1;
        float sum0 = 0.f, sum1 = 0.f;
#pragma unroll
        for (int nt = 0; nt < 8; nt++) {
            accS[nt][0] = __expf(accS[nt][0] - mn0);
            accS[nt][1] = __expf(accS[nt][1] - mn0);
            accS[nt][2] = __expf(accS[nt][2] - mn1);
            accS[nt][3] = __expf(accS[nt][3] - mn1);
            sum0 += accS[nt][0] + accS[nt][1];
            sum1 += accS[nt][2] + accS[nt][3];
        }
        sum0 += __shfl_xor_sync(0xffffffffu, sum0, 1);
        sum0 += __shfl_xor_sync(0xffffffffu, sum0, 2);
        sum1 += __shfl_xor_sync(0xffffffffu, sum1, 1);
        sum1 += __shfl_xor_sync(0xffffffffu, sum1, 2);
        l0 = l0 * al0 + sum0;
        l1 = l1 * al1 + sum1;

        // ---- O = O*alpha + P @ V ----
#pragma unroll
        for (int nt = 0; nt < 8; nt++) {
            accO[nt][0] *= al0; accO[nt][1] *= al0;
            accO[nt][2] *= al1; accO[nt][3] *= al1;
        }
        const uint32_t bV = sb + AT_KVOFF + st * AT_STAGE + AT_KTILE
                          + t * AT_VRB + (g << 2);
#pragma unroll
        for (int kc = 0; kc < 8; kc++) {
            float x0 = __shfl_sync(0xffffffffu, accS[kc][0], src_lo);
            float x1 = __shfl_sync(0xffffffffu, accS[kc][1], src_lo);
            float y0 = __shfl_sync(0xffffffffu, accS[kc][0], src_hi);
            float y1 = __shfl_sync(0xffffffffu, accS[kc][1], src_hi);
            float z0 = __shfl_sync(0xffffffffu, accS[kc][2], src_lo);
            float z1 = __shfl_sync(0xffffffffu, accS[kc][3], src_lo);
            float u0 = __shfl_sync(0xffffffffu, accS[kc][2], src_hi);
            float u1 = __shfl_sync(0xffffffffu, accS[kc][3], src_hi);
            uint32_t a_[4];
            a_[0] = __float_as_uint((t & 1) ? x1 : x0);
            a_[1] = __float_as_uint((t & 1) ? z1 : z0);
            a_[2] = __float_as_uint((t & 1) ? y1 : y0);
            a_[3] = __float_as_uint((t & 1) ? u1 : u0);
#pragma unroll
            for (int nt = 0; nt < 8; nt++) {
                uint32_t b_[2];
                uint32_t ba = bV + kc * 8 * AT_VRB + (nt << 5);
                b_[0] = lds32(ba);
                b_[1] = lds32(ba + 4 * AT_VRB);
                mma_tf32(accO[nt], a_, b_);
            }
        }
    }

    // ---- write ctx = O / l ----
    {
        const int r0 = w16 + g, r1 = r0 + 8;
        float inv0 = 1.0f / l0;
        float inv1 = 1.0f / l1;
        float* obase = ctx + (size_t)b * SEQ * DIM + h * HDIM;
        float* o0 = &obase[(size_t)(qt * 64 + r0) * DIM];
        float* o1 = &obase[(size_t)(qt * 64 + r1) * DIM];
#pragma unroll
        for (int nt = 0; nt < 8; nt++) {
            int c = nt * 8 + (t << 1);
            *(float2*)&o0[c] = make_float2(accO[nt][0] * inv0, accO[nt][1] * inv0);
            *(float2*)&o1[c] = make_float2(accO[nt][2] * inv1, accO[nt][3] * inv1);
        }
    }
}

// ---------------- launch ------------------------------------------------------
static float* dev_ptr(const void* sym)
{
    void* p = nullptr;
    cudaGetSymbolAddress(&p, sym);
    return (float*)p;
}

extern "C" void kernel_launch(void* const* d_in, const int* in_sizes, int n_in,
                              void* d_out, int out_size)
{
    (void)in_sizes; (void)n_in; (void)out_size;
    const float* x   = (const float*)d_in[0];
    const float* wq  = (const float*)d_in[1];
    const float* wk  = (const float*)d_in[2];
    const float* wv  = (const float*)d_in[3];
    const float* wo  = (const float*)d_in[4];
    const float* bo  = (const float*)d_in[5];
    const float* w1  = (const float*)d_in[6];
    const float* b1  = (const float*)d_in[7];
    const float* w2  = (const float*)d_in[8];
    const float* b2  = (const float*)d_in[9];
    const float* g1  = (const float*)d_in[10];
    const float* be1 = (const float*)d_in[11];
    const float* g2  = (const float*)d_in[12];
    const float* be2 = (const float*)d_in[13];
    float* out = (float*)d_out;

    float* h    = dev_ptr(g_h);
    float* qb   = dev_ptr(g_q);
    float* kb   = dev_ptr(g_k);
    float* vb   = dev_ptr(g_v);
    float* ctx  = dev_ptr(g_ctx);
    float* x1   = dev_ptr(g_x1);
    float* ff   = dev_ptr(g_ff);
    float* wqT  = dev_ptr(g_wqT);
    float* wkT  = dev_ptr(g_wkT);
    float* wvT  = dev_ptr(g_wvT);
    float* woT  = dev_ptr(g_woT);
    float* w1T  = dev_ptr(g_w1T);
    float* w2T  = dev_ptr(g_w2T);

    cudaFuncSetAttribute(attn_mma_kernel, cudaFuncAttributeMaxDynamicSharedMemorySize, ATTN_SMEM);
    cudaFuncSetAttribute(qkv_gemm_kernel,
                         cudaFuncAttributeMaxDynamicSharedMemorySize, GEMM_SMEM);
    cudaFuncSetAttribute(tf32_gemm_kernel<false, true, true>,
                         cudaFuncAttributeMaxDynamicSharedMemorySize, GEMM_SMEM);
    cudaFuncSetAttribute(tf32_gemm_kernel<true, true, false>,
                         cudaFuncAttributeMaxDynamicSharedMemorySize, GEMM_SMEM);

    // all weight transposes in one launch
    transpose_all_kernel<<<1728, dim3(32, 8)>>>(wq, wk, wv, wo, w1, w2,
                                                wqT, wkT, wvT, woT, w1T, w2T);
    // LN1
    ln_kernel<<<NTOK / 8, 256>>>(x, g1, be1, h);
    // fused QKV projections
    qkv_gemm_kernel<<<dim3(NTOK / 128, 9), 256, GEMM_SMEM>>>(h, wqT, wkT, wvT, qb, kb, vb);
    // attention (tf32 mma)
    attn_mma_kernel<<<dim3(SEQ / 64, NHEAD, BATCH), 128, ATTN_SMEM>>>(qb, kb, vb, ctx);
    // output projection + residual
    tf32_gemm_kernel<false, true, true><<<dim3(NTOK / 128, 3), 256, GEMM_SMEM>>>(ctx, woT, bo, x, x1, DIM, DIM);
    // LN2
    ln_kernel<<<NTOK / 8, 256>>>(x1, g2, be2, h);
    // FFN
    tf32_gemm_kernel<true, true, false><<<dim3(NTOK / 128, 12), 256, GEMM_SMEM>>>(h, w1T, b1, nullptr, ff, DIM, FFDIM);
    tf32_gemm_kernel<false, true, true><<<dim3(NTOK / 128, 3), 256, GEMM_SMEM>>>(ff, w2T, b2, x1, out, FFDIM, DIM);
}

// round 11
// speedup vs baseline: 1.3182x; 1.0072x over previous
#include <cuda_runtime.h>
#include <cuda_bf16.h>
#include <cstdint>
#include <math.h>

// Problem dims
#define BATCH 64
#define SEQ   256
#define DIM   384
#define NHEAD 6
#define HDIM  64
#define NTOK  (BATCH * SEQ)      // 16384
#define FFDIM (4 * DIM)          // 1536

// ---------------- scratch (static device globals; no allocation) -------------
__device__ float g_h  [NTOK * DIM];
__device__ float g_q  [NTOK * DIM];
__device__ float g_k  [NTOK * DIM];
__device__ float g_v  [NTOK * DIM];
__device__ float g_ctx[NTOK * DIM];
__device__ float g_x1 [NTOK * DIM];
__device__ float g_ff [NTOK * FFDIM];
// transposed weights [M][K]
__device__ float g_wqT[DIM * DIM];
__device__ float g_wkT[DIM * DIM];
__device__ float g_wvT[DIM * DIM];
__device__ float g_woT[DIM * DIM];
__device__ float g_w1T[DIM * FFDIM];
__device__ float g_w2T[FFDIM * DIM];

// ---------------- PTX helpers -------------------------------------------------
__device__ __forceinline__ uint32_t smem_u32(const void* p) {
    uint32_t a;
    asm("{ .reg .u64 t; cvta.to.shared.u64 t, %1; cvt.u32.u64 %0, t; }"
        : "=r"(a) : "l"(p));
    return a;
}
__device__ __forceinline__ void cp_async16(uint32_t dst, const void* src) {
    asm volatile("cp.async.cg.shared.global [%0], [%1], 16;" :: "r"(dst), "l"(src));
}
__device__ __forceinline__ void cp_commit() {
    asm volatile("cp.async.commit_group;" ::: "memory");
}
template<int N> __device__ __forceinline__ void cp_wait() {
    asm volatile("cp.async.wait_group %0;" :: "n"(N) : "memory");
}
__device__ __forceinline__ void mma_tf32(float* c, const uint32_t* a, const uint32_t* b) {
    asm volatile(
        "mma.sync.aligned.m16n8k8.row.col.f32.tf32.tf32.f32 "
        "{%0,%1,%2,%3}, {%4,%5,%6,%7}, {%8,%9}, {%0,%1,%2,%3};"
        : "+f"(c[0]), "+f"(c[1]), "+f"(c[2]), "+f"(c[3])
        : "r"(a[0]), "r"(a[1]), "r"(a[2]), "r"(a[3]), "r"(b[0]), "r"(b[1]));
}
__device__ __forceinline__ void ldsm_x4(uint32_t& r0, uint32_t& r1, uint32_t& r2,
                                        uint32_t& r3, uint32_t addr) {
    asm volatile("ldmatrix.sync.aligned.m8n8.x4.shared.b16 {%0,%1,%2,%3}, [%4];"
                 : "=r"(r0), "=r"(r1), "=r"(r2), "=r"(r3) : "r"(addr));
}
__device__ __forceinline__ uint32_t lds32(uint32_t addr) {
    uint32_t v;
    asm volatile("ld.shared.b32 %0, [%1];" : "=r"(v) : "r"(addr));
    return v;
}

// ================= tf32 mma.sync GEMM, cp.async 3-stage + ldmatrix ===========
#define BK       32
#define STRD     144                      // bytes per smem row (36 floats)
#define SA_BYTES (128 * STRD)             // 18432
#define SB_BYTES (128 * STRD)             // 18432
#define STAGE_BYTES (SA_BYTES + SB_BYTES) // 36864
#define STAGES   3
#define GEMM_SMEM (STAGES * STAGE_BYTES)  // 110592

template<bool RELU, bool BIAS, bool RESID>
__device__ __forceinline__ void gemm_body(
    uint32_t sb,
    const float* __restrict__ A, const float* __restrict__ WT,
    const float* __restrict__ bias, const float* __restrict__ resid,
    float* __restrict__ C, int K, int M, int row0, int col0)
{
    const int tid  = threadIdx.x;
    const int wid  = tid >> 5;
    const int lane = tid & 31;
    const int warpM = wid & 1;
    const int warpN = wid >> 1;
    const int g = lane >> 2, t = lane & 3;

    const int laneRowA = ((lane >> 3) & 1) * 8 + (lane & 7);
    const int laneKA   = (lane >> 4) * 16;
    const int laneRowB = (lane >> 4) * 8 + (lane & 7);
    const int laneKB   = ((lane >> 3) & 1) * 16;

    float acc[4][4][4];
#pragma unroll
    for (int mt = 0; mt < 4; mt++)
#pragma unroll
        for (int nt = 0; nt < 4; nt++)
#pragma unroll
            for (int f = 0; f < 4; f++) acc[mt][nt][f] = 0.f;

    const int KT = K >> 5;

    auto copy_stage = [&](int kt, int st) {
        const int k0 = kt << 5;
        const uint32_t abase = sb + st * STAGE_BYTES;
        const uint32_t bbase = abase + SA_BYTES;
#pragma unroll
        for (int i = 0; i < 4; i++) {
            int c = tid + (i << 8);
            int r = c >> 3, k4 = c & 7;
            cp_async16(abase + r * STRD + (k4 << 4),
                       &A[(size_t)(row0 + r) * K + k0 + (k4 << 2)]);
        }
#pragma unroll
        for (int i = 0; i < 4; i++) {
            int c = tid + (i << 8);
            int n = c >> 3, k4 = c & 7;
            cp_async16(bbase + n * STRD + (k4 << 4),
                       &WT[(size_t)(col0 + n) * K + k0 + (k4 << 2)]);
        }
    };

    copy_stage(0, 0); cp_commit();
    copy_stage(1, 1); cp_commit();

    for (int kt = 0; kt < KT; kt++) {
        const int st = kt % STAGES;
        cp_wait<1>();
        __syncthreads();
        if (kt + 2 < KT) copy_stage(kt + 2, (kt + 2) % STAGES);
        cp_commit();

        const uint32_t aB = sb + st * STAGE_BYTES
                          + (warpM * 64 + laneRowA) * STRD + laneKA;
        const uint32_t bB = sb + st * STAGE_BYTES + SA_BYTES
                          + (warpN * 32 + laneRowB) * STRD + laneKB;
#pragma unroll
        for (int kc = 0; kc < 4; kc++) {
            uint32_t a_[4][4], b_[4][2];
#pragma unroll
            for (int mt = 0; mt < 4; mt++)
                ldsm_x4(a_[mt][0], a_[mt][1], a_[mt][2], a_[mt][3],
                        aB + mt * 16 * STRD + (kc << 5));
            ldsm_x4(b_[0][0], b_[0][1], b_[1][0], b_[1][1], bB + (kc << 5));
            ldsm_x4(b_[2][0], b_[2][1], b_[3][0], b_[3][1],
                    bB + 16 * STRD + (kc << 5));
#pragma unroll
            for (int mt = 0; mt < 4; mt++)
#pragma unroll
                for (int nt = 0; nt < 4; nt++)
                    mma_tf32(acc[mt][nt], a_[mt], b_[nt]);
        }
    }

#pragma unroll
    for (int mt = 0; mt < 4; mt++) {
        int r_lo = row0 + warpM * 64 + mt * 16 + g;
        int r_hi = r_lo + 8;
#pragma unroll
        for (int nt = 0; nt < 4; nt++) {
            int col = col0 + warpN * 32 + nt * 8 + (t << 1);
            float2 v0 = make_float2(acc[mt][nt][0], acc[mt][nt][1]);
            float2 v1 = make_float2(acc[mt][nt][2], acc[mt][nt][3]);
            if (BIAS) {
                float2 bv = *(const float2*)&bias[col];
                v0.x += bv.x; v0.y += bv.y;
                v1.x += bv.x; v1.y += bv.y;
            }
            if (RESID) {
                float2 q0 = *(const float2*)&resid[(size_t)r_lo * M + col];
                float2 q1 = *(const float2*)&resid[(size_t)r_hi * M + col];
                v0.x += q0.x; v0.y += q0.y;
                v1.x += q1.x; v1.y += q1.y;
            }
            if (RELU) {
                v0.x = fmaxf(v0.x, 0.f); v0.y = fmaxf(v0.y, 0.f);
                v1.x = fmaxf(v1.x, 0.f); v1.y = fmaxf(v1.y, 0.f);
            }
            *(float2*)&C[(size_t)r_lo * M + col] = v0;
            *(float2*)&C[(size_t)r_hi * M + col] = v1;
        }
    }
}

template<bool RELU, bool BIAS, bool RESID>
__global__ void __launch_bounds__(256, 2)
tf32_gemm_kernel(const float* __restrict__ A, const float* __restrict__ WT,
                 const float* __restrict__ bias, const float* __restrict__ resid,
                 float* __restrict__ C, int K, int M)
{
    extern __shared__ char smem[];
    gemm_body<RELU, BIAS, RESID>(smem_u32(smem), A, WT, bias, resid, C, K, M,
                                 blockIdx.x * 128, blockIdx.y * 128);
}

__global__ void __launch_bounds__(256, 2)
qkv_gemm_kernel(const float* __restrict__ A,
                const float* __restrict__ wqT, const float* __restrict__ wkT,
                const float* __restrict__ wvT,
                float* __restrict__ q, float* __restrict__ k, float* __restrict__ v)
{
    extern __shared__ char smem[];
    int y = blockIdx.y;
    int sel = y / 3;
    int col0 = (y - sel * 3) * 128;
    const float* WT = (sel == 0) ? wqT : (sel == 1) ? wkT : wvT;
    float* C = (sel == 0) ? q : (sel == 1) ? k : v;
    gemm_body<false, false, false>(smem_u32(smem), A, WT, nullptr, nullptr, C,
                                   DIM, DIM, blockIdx.x * 128, col0);
}

// ---------------- merged weight transpose (1 launch, 1728 tiles) --------------
__global__ void transpose_all_kernel(
    const float* __restrict__ wq, const float* __restrict__ wk,
    const float* __restrict__ wv, const float* __restrict__ wo,
    const float* __restrict__ w1, const float* __restrict__ w2,
    float* __restrict__ wqT, float* __restrict__ wkT,
    float* __restrict__ wvT, float* __restrict__ woT,
    float* __restrict__ w1T, float* __restrict__ w2T)
{
    __shared__ float tbuf[32][33];
    int id = blockIdx.x;
    const float* in; float* out; int R, C, bx, by;
    if (id < 576) {
        int m = id / 144, r = id - m * 144;
        switch (m) {
            case 0: in = wq; out = wqT; break;
            case 1: in = wk; out = wkT; break;
            case 2: in = wv; out = wvT; break;
            default: in = wo; out = woT; break;
        }
        R = DIM; C = DIM; bx = (r % 12) * 32; by = (r / 12) * 32;
    } else if (id < 1152) {
        int r = id - 576;
        in = w1; out = w1T; R = DIM; C = FFDIM;
        bx = (r % 48) * 32; by = (r / 48) * 32;
    } else {
        int r = id - 1152;
        in = w2; out = w2T; R = FFDIM; C = DIM;
        bx = (r % 12) * 32; by = (r / 12) * 32;
    }
#pragma unroll
    for (int i = 0; i < 32; i += 8)
        tbuf[threadIdx.y + i][threadIdx.x] =
            in[(size_t)(by + threadIdx.y + i) * C + bx + threadIdx.x];
    __syncthreads();
#pragma unroll
    for (int i = 0; i < 32; i += 8)
        out[(size_t)(bx + threadIdx.y + i) * R + by + threadIdx.x] =
            tbuf[threadIdx.x][threadIdx.y + i];
}

// ---------------- LayerNorm (vectorized float4) -------------------------------
__global__ void ln_kernel(const float* __restrict__ x,
                          const float* __restrict__ g,
                          const float* __restrict__ be,
                          float* __restrict__ out)
{
    int warp = (blockIdx.x * blockDim.x + threadIdx.x) >> 5;
    int lane = threadIdx.x & 31;
    if (warp >= NTOK) return;
    const float4* row = (const float4*)(x + (size_t)warp * DIM);
    float4 v[3];
    float s = 0.f, ss = 0.f;
#pragma unroll
    for (int i = 0; i < 3; i++) {
        v[i] = row[lane + 32 * i];
        s  += v[i].x + v[i].y + v[i].z + v[i].w;
        ss += v[i].x * v[i].x + v[i].y * v[i].y + v[i].z * v[i].z + v[i].w * v[i].w;
    }
#pragma unroll
    for (int o = 16; o; o >>= 1) {
        s  += __shfl_xor_sync(0xffffffffu, s, o);
        ss += __shfl_xor_sync(0xffffffffu, ss, o);
    }
    float mean = s * (1.0f / DIM);
    float var  = ss * (1.0f / DIM) - mean * mean;
    float rstd = rsqrtf(var + 1e-5f);
    float4* orow = (float4*)(out + (size_t)warp * DIM);
#pragma unroll
    for (int i = 0; i < 3; i++) {
        int c4 = lane + 32 * i;
        float4 gv = *(const float4*)&g[c4 * 4];
        float4 bv = *(const float4*)&be[c4 * 4];
        float4 o;
        o.x = (v[i].x - mean) * rstd * gv.x + bv.x;
        o.y = (v[i].y - mean) * rstd * gv.y + bv.y;
        o.z = (v[i].z - mean) * rstd * gv.z + bv.z;
        o.w = (v[i].w - mean) * rstd * gv.w + bv.w;
        orow[c4] = o;
    }
}

// ---------------- Tensor-core causal flash attention --------------------------
// 64 queries/CTA, 128 threads, 3 CTAs/SM. Q tile ALIASED with KV stage-1 (Q is
// consumed into register fragments before stage-1 is ever written). Layout:
//   [0, 35840)       stage 1 (K then V);  Q occupies [0, 17408) transiently
//   [35840, 71680)   stage 0
// K stride 68 floats (conflict-free ldmatrix), V stride 72 (bank 8t+g bijective)
#define AT_RS    68
#define AT_RB    (AT_RS * 4)               // 272
#define AT_VRB   (72 * 4)                  // 288
#define AT_KTILE (64 * AT_RB)              // 17408
#define AT_VTILE (64 * AT_VRB)             // 18432
#define AT_STAGE (AT_KTILE + AT_VTILE)     // 35840
#define ATTN_SMEM (2 * AT_STAGE)           // 71680

__global__ void __launch_bounds__(128, 3)
attn_mma_kernel(const float* __restrict__ q, const float* __restrict__ k,
                const float* __restrict__ v, float* __restrict__ ctx)
{
    extern __shared__ float sm[];
    const uint32_t sb = smem_u32(sm);

    const int qt = blockIdx.x;
    const int h  = blockIdx.y;
    const int b  = blockIdx.z;
    const int tid = threadIdx.x;
    const int wid = tid >> 5;
    const int lane = tid & 31;
    const int g = lane >> 2, t = lane & 3;
    const int w16 = wid * 16;

    const int laneRowA = ((lane >> 3) & 1) * 8 + (lane & 7);
    const int laneKA   = (lane >> 4) * 16;
    const int laneRowB = (lane >> 4) * 8 + (lane & 7);
    const int laneKB   = ((lane >> 3) & 1) * 16;

    const float* qbase = q + (size_t)b * SEQ * DIM + h * HDIM;
    const float* kbase = k + (size_t)b * SEQ * DIM + h * HDIM;
    const float* vbase = v + (size_t)b * SEQ * DIM + h * HDIM;

    // stage offsets: st0 -> +AT_STAGE, st1 -> +0 (aliases Q)
    auto stage_off = [&](int st) -> uint32_t {
        return st ? 0u : (uint32_t)AT_STAGE;
    };

    // Q tile cp.async into [0, 17408)
#pragma unroll
    for (int i = 0; i < 8; i++) {
        int f = tid + (i << 7);
        int r = f >> 4, d4 = (f & 15) << 2;
        cp_async16(sb + r * AT_RB + (d4 << 2),
                   &qbase[(size_t)(qt * 64 + r) * DIM + d4]);
    }
    auto copy_kv = [&](int kt, int st) {
        const uint32_t kdst = sb + stage_off(st);
        const uint32_t vdst = kdst + AT_KTILE;
#pragma unroll
        for (int i = 0; i < 8; i++) {
            int f = tid + (i << 7);
            int r = f >> 4, d4 = (f & 15) << 2;
            cp_async16(kdst + r * AT_RB + (d4 << 2),
                       &kbase[(size_t)(kt * 64 + r) * DIM + d4]);
        }
#pragma unroll
        for (int i = 0; i < 8; i++) {
            int f = tid + (i << 7);
            int r = f >> 4, d4 = (f & 15) << 2;
            cp_async16(vdst + r * AT_VRB + (d4 << 2),
                       &vbase[(size_t)(kt * 64 + r) * DIM + d4]);
        }
    };

    copy_kv(0, 0);               // stage 0 region (no overlap with Q)
    cp_commit();
    cp_wait<0>();
    __syncthreads();

    // hoist Q A-fragments (8 kc x 4 regs)
    uint32_t qfrag[8][4];
    {
        const uint32_t aQ = sb + (w16 + laneRowA) * AT_RB + laneKA;
#pragma unroll
        for (int kc = 0; kc < 8; kc++)
            ldsm_x4(qfrag[kc][0], qfrag[kc][1], qfrag[kc][2], qfrag[kc][3],
                    aQ + (kc << 5));
    }
    __syncthreads();             // all warps done reading Q before stage-1 fill

    float m0 = -1e30f, m1 = -1e30f, l0 = 0.f, l1 = 0.f;
    float accO[8][4];
#pragma unroll
    for (int nt = 0; nt < 8; nt++)
#pragma unroll
        for (int f = 0; f < 4; f++) accO[nt][f] = 0.f;

    const int gq0 = qt * 64 + w16 + g;
    const int gq1 = gq0 + 8;
    const int src_lo = (lane & ~3) | (t >> 1);
    const int src_hi = src_lo + 2;

    const int KT = qt + 1;
    for (int kt = 0; kt < KT; kt++) {
        const int st = kt & 1;
        if (kt > 0) {
            cp_wait<0>();
            __syncthreads();
        }
        if (kt + 1 < KT) {
            copy_kv(kt + 1, st ^ 1);
            cp_commit();
        }

        // ---- S = Q @ K^T (K via ldmatrix) ----
        float accS[8][4];
#pragma unroll
        for (int nt = 0; nt < 8; nt++)
#pragma unroll
            for (int f = 0; f < 4; f++) accS[nt][f] = 0.f;

        const uint32_t bK = sb + stage_off(st) + laneRowB * AT_RB + laneKB;
#pragma unroll
        for (int kc = 0; kc < 8; kc++) {
            uint32_t b_[8][2];
#pragma unroll
            for (int p = 0; p < 4; p++)
                ldsm_x4(b_[2 * p][0], b_[2 * p][1], b_[2 * p + 1][0], b_[2 * p + 1][1],
                        bK + p * 16 * AT_RB + (kc << 5));
#pragma unroll
            for (int nt = 0; nt < 8; nt++)
                mma_tf32(accS[nt], qfrag[kc], b_[nt]);
        }

        // ---- mask + scale (in registers) ----
#pragma unroll
        for (int nt = 0; nt < 8; nt++) {
            int gk = kt * 64 + nt * 8 + (t << 1);
            accS[nt][0] = (gk     > gq0) ? -1e30f : accS[nt][0] * 0.125f;
            accS[nt][1] = (gk + 1 > gq0) ? -1e30f : accS[nt][1] * 0.125f;
            accS[nt][2] = (gk     > gq1) ? -1e30f : accS[nt][2] * 0.125f;
            accS[nt][3] = (gk + 1 > gq1) ? -1e30f : accS[nt][3] * 0.125f;
        }

        // ---- register softmax ----
        float pm0 = -1e30f, pm1 = -1e30f;
#pragma unroll
        for (int nt = 0; nt < 8; nt++) {
            pm0 = fmaxf(pm0, fmaxf(accS[nt][0], accS[nt][1]));
            pm1 = fmaxf(pm1, fmaxf(accS[nt][2], accS[nt][3]));
        }
        pm0 = fmaxf(pm0, __shfl_xor_sync(0xffffffffu, pm0, 1));
        pm0 = fmaxf(pm0, __shfl_xor_sync(0xffffffffu, pm0, 2));
        pm1 = fmaxf(pm1, __shfl_xor_sync(0xffffffffu, pm1, 1));
        pm1 = fmaxf(pm1, __shfl_xor_sync(0xffffffffu, pm1, 2));
        float mn0 = fmaxf(m0, pm0), mn1 = fmaxf(m1, pm1);
        float al0 = __expf(m0 - mn0), al1 = __expf(m1 - mn1);
        m0 = mn0; m1 = mn1;
        float sum0 = 0.f, sum1 = 0.f;
#pragma unroll
        for (int nt = 0; nt < 8; nt++) {
            accS[nt][0] = __expf(accS[nt][0] - mn0);
            accS[nt][1] = __expf(accS[nt][1] - mn0);
            accS[nt][2] = __expf(accS[nt][2] - mn1);
            accS[nt][3] = __expf(accS[nt][3] - mn1);
            sum0 += accS[nt][0] + accS[nt][1];
            sum1 += accS[nt][2] + accS[nt][3];
        }
        sum0 += __shfl_xor_sync(0xffffffffu, sum0, 1);
        sum0 += __shfl_xor_sync(0xffffffffu, sum0, 2);
        sum1 += __shfl_xor_sync(0xffffffffu, sum1, 1);
        sum1 += __shfl_xor_sync(0xffffffffu, sum1, 2);
        l0 = l0 * al0 + sum0;
        l1 = l1 * al1 + sum1;

        // ---- O = O*alpha + P @ V ----
#pragma unroll
        for (int nt = 0; nt < 8; nt++) {
            accO[nt][0] *= al0; accO[nt][1] *= al0;
            accO[nt][2] *= al1; accO[nt][3] *= al1;
        }
        const uint32_t bV = sb + stage_off(st) + AT_KTILE
                          + t * AT_VRB + (g << 2);
#pragma unroll
        for (int kc = 0; kc < 8; kc++) {
            float x0 = __shfl_sync(0xffffffffu, accS[kc][0], src_lo);
            float x1 = __shfl_sync(0xffffffffu, accS[kc][1], src_lo);
            float y0 = __shfl_sync(0xffffffffu, accS[kc][0], src_hi);
            float y1 = __shfl_sync(0xffffffffu, accS[kc][1], src_hi);
            float z0 = __shfl_sync(0xffffffffu, accS[kc][2], src_lo);
            float z1 = __shfl_sync(0xffffffffu, accS[kc][3], src_lo);
            float u0 = __shfl_sync(0xffffffffu, accS[kc][2], src_hi);
            float u1 = __shfl_sync(0xffffffffu, accS[kc][3], src_hi);
            uint32_t a_[4];
            a_[0] = __float_as_uint((t & 1) ? x1 : x0);
            a_[1] = __float_as_uint((t & 1) ? z1 : z0);
            a_[2] = __float_as_uint((t & 1) ? y1 : y0);
            a_[3] = __float_as_uint((t & 1) ? u1 : u0);
#pragma unroll
            for (int nt = 0; nt < 8; nt++) {
                uint32_t b_[2];
                uint32_t ba = bV + kc * 8 * AT_VRB + (nt << 5);
                b_[0] = lds32(ba);
                b_[1] = lds32(ba + 4 * AT_VRB);
                mma_tf32(accO[nt], a_, b_);
            }
        }
    }

    // ---- write ctx = O / l ----
    {
        const int r0 = w16 + g, r1 = r0 + 8;
        float inv0 = 1.0f / l0;
        float inv1 = 1.0f / l1;
        float* obase = ctx + (size_t)b * SEQ * DIM + h * HDIM;
        float* o0 = &obase[(size_t)(qt * 64 + r0) * DIM];
        float* o1 = &obase[(size_t)(qt * 64 + r1) * DIM];
#pragma unroll
        for (int nt = 0; nt < 8; nt++) {
            int c = nt * 8 + (t << 1);
            *(float2*)&o0[c] = make_float2(accO[nt][0] * inv0, accO[nt][1] * inv0);
            *(float2*)&o1[c] = make_float2(accO[nt][2] * inv1, accO[nt][3] * inv1);
        }
    }
}

// ---------------- launch ------------------------------------------------------
static float* dev_ptr(const void* sym)
{
    void* p = nullptr;
    cudaGetSymbolAddress(&p, sym);
    return (float*)p;
}

extern "C" void kernel_launch(void* const* d_in, const int* in_sizes, int n_in,
                              void* d_out, int out_size)
{
    (void)in_sizes; (void)n_in; (void)out_size;
    const float* x   = (const float*)d_in[0];
    const float* wq  = (const float*)d_in[1];
    const float* wk  = (const float*)d_in[2];
    const float* wv  = (const float*)d_in[3];
    const float* wo  = (const float*)d_in[4];
    const float* bo  = (const float*)d_in[5];
    const float* w1  = (const float*)d_in[6];
    const float* b1  = (const float*)d_in[7];
    const float* w2  = (const float*)d_in[8];
    const float* b2  = (const float*)d_in[9];
    const float* g1  = (const float*)d_in[10];
    const float* be1 = (const float*)d_in[11];
    const float* g2  = (const float*)d_in[12];
    const float* be2 = (const float*)d_in[13];
    float* out = (float*)d_out;

    float* h    = dev_ptr(g_h);
    float* qb   = dev_ptr(g_q);
    float* kb   = dev_ptr(g_k);
    float* vb   = dev_ptr(g_v);
    float* ctx  = dev_ptr(g_ctx);
    float* x1   = dev_ptr(g_x1);
    float* ff   = dev_ptr(g_ff);
    float* wqT  = dev_ptr(g_wqT);
    float* wkT  = dev_ptr(g_wkT);
    float* wvT  = dev_ptr(g_wvT);
    float* woT  = dev_ptr(g_woT);
    float* w1T  = dev_ptr(g_w1T);
    float* w2T  = dev_ptr(g_w2T);

    cudaFuncSetAttribute(attn_mma_kernel, cudaFuncAttributeMaxDynamicSharedMemorySize, ATTN_SMEM);
    cudaFuncSetAttribute(qkv_gemm_kernel,
                         cudaFuncAttributeMaxDynamicSharedMemorySize, GEMM_SMEM);
    cudaFuncSetAttribute(tf32_gemm_kernel<false, true, true>,
                         cudaFuncAttributeMaxDynamicSharedMemorySize, GEMM_SMEM);
    cudaFuncSetAttribute(tf32_gemm_kernel<true, true, false>,
                         cudaFuncAttributeMaxDynamicSharedMemorySize, GEMM_SMEM);

    // all weight transposes in one launch
    transpose_all_kernel<<<1728, dim3(32, 8)>>>(wq, wk, wv, wo, w1, w2,
                                                wqT, wkT, wvT, woT, w1T, w2T);
    // LN1
    ln_kernel<<<NTOK / 8, 256>>>(x, g1, be1, h);
    // fused QKV projections
    qkv_gemm_kernel<<<dim3(NTOK / 128, 9), 256, GEMM_SMEM>>>(h, wqT, wkT, wvT, qb, kb, vb);
    // attention (tf32 mma)
    attn_mma_kernel<<<dim3(SEQ / 64, NHEAD, BATCH), 128, ATTN_SMEM>>>(qb, kb, vb, ctx);
    // output projection + residual
    tf32_gemm_kernel<false, true, true><<<dim3(NTOK / 128, 3), 256, GEMM_SMEM>>>(ctx, woT, bo, x, x1, DIM, DIM);
    // LN2
    ln_kernel<<<NTOK / 8, 256>>>(x1, g2, be2, h);
    // FFN
    tf32_gemm_kernel<true, true, false><<<dim3(NTOK / 128, 12), 256, GEMM_SMEM>>>(h, w1T, b1, nullptr, ff, DIM, FFDIM);
    tf32_gemm_kernel<false, true, true><<<dim3(NTOK / 128, 3), 256, GEMM_SMEM>>>(ff, w2T, b2, x1, out, FFDIM, DIM);
}

// round 12
// speedup vs baseline: 1.9768x; 1.4996x over previous
#include <cuda_runtime.h>
#include <cuda_bf16.h>
#include <cstdint>
#include <math.h>

// Problem dims
#define BATCH 64
#define SEQ   256
#define DIM   384
#define NHEAD 6
#define HDIM  64
#define NTOK  (BATCH * SEQ)      // 16384
#define FFDIM (4 * DIM)          // 1536

// ---------------- scratch (static device globals; no allocation) -------------
__device__ __nv_bfloat16 g_hb [NTOK * DIM];    // LN out (bf16, GEMM A operand)
__device__ float         g_q  [NTOK * DIM];
__device__ float         g_k  [NTOK * DIM];
__device__ float         g_v  [NTOK * DIM];
__device__ __nv_bfloat16 g_ctxb[NTOK * DIM];   // attention out (bf16)
__device__ float         g_x1 [NTOK * DIM];
__device__ __nv_bfloat16 g_ffb[NTOK * FFDIM];  // FFN hidden (bf16)
// transposed weights [M][K] in bf16
__device__ __nv_bfloat16 g_wqT[DIM * DIM];
__device__ __nv_bfloat16 g_wkT[DIM * DIM];
__device__ __nv_bfloat16 g_wvT[DIM * DIM];
__device__ __nv_bfloat16 g_woT[DIM * DIM];
__device__ __nv_bfloat16 g_w1T[DIM * FFDIM];
__device__ __nv_bfloat16 g_w2T[FFDIM * DIM];

// ---------------- PTX helpers -------------------------------------------------
__device__ __forceinline__ uint32_t smem_u32(const void* p) {
    uint32_t a;
    asm("{ .reg .u64 t; cvta.to.shared.u64 t, %1; cvt.u32.u64 %0, t; }"
        : "=r"(a) : "l"(p));
    return a;
}
__device__ __forceinline__ void cp_async16(uint32_t dst, const void* src) {
    asm volatile("cp.async.cg.shared.global [%0], [%1], 16;" :: "r"(dst), "l"(src));
}
__device__ __forceinline__ void cp_commit() {
    asm volatile("cp.async.commit_group;" ::: "memory");
}
template<int N> __device__ __forceinline__ void cp_wait() {
    asm volatile("cp.async.wait_group %0;" :: "n"(N) : "memory");
}
__device__ __forceinline__ void mma_tf32(float* c, const uint32_t* a, const uint32_t* b) {
    asm volatile(
        "mma.sync.aligned.m16n8k8.row.col.f32.tf32.tf32.f32 "
        "{%0,%1,%2,%3}, {%4,%5,%6,%7}, {%8,%9}, {%0,%1,%2,%3};"
        : "+f"(c[0]), "+f"(c[1]), "+f"(c[2]), "+f"(c[3])
        : "r"(a[0]), "r"(a[1]), "r"(a[2]), "r"(a[3]), "r"(b[0]), "r"(b[1]));
}
__device__ __forceinline__ void mma_bf16(float* c, const uint32_t* a, const uint32_t* b) {
    asm volatile(
        "mma.sync.aligned.m16n8k16.row.col.f32.bf16.bf16.f32 "
        "{%0,%1,%2,%3}, {%4,%5,%6,%7}, {%8,%9}, {%0,%1,%2,%3};"
        : "+f"(c[0]), "+f"(c[1]), "+f"(c[2]), "+f"(c[3])
        : "r"(a[0]), "r"(a[1]), "r"(a[2]), "r"(a[3]), "r"(b[0]), "r"(b[1]));
}
__device__ __forceinline__ void ldsm_x4(uint32_t& r0, uint32_t& r1, uint32_t& r2,
                                        uint32_t& r3, uint32_t addr) {
    asm volatile("ldmatrix.sync.aligned.m8n8.x4.shared.b16 {%0,%1,%2,%3}, [%4];"
                 : "=r"(r0), "=r"(r1), "=r"(r2), "=r"(r3) : "r"(addr));
}
__device__ __forceinline__ uint32_t lds32(uint32_t addr) {
    uint32_t v;
    asm volatile("ld.shared.b32 %0, [%1];" : "=r"(v) : "r"(addr));
    return v;
}

// ================= bf16 mma.sync GEMM, cp.async 3-stage + ldmatrix ===========
// A: [N,K] bf16 row-major, WT: [M,K] bf16 row-major, C = act(A@W+bias+resid).
// CTA 128x128, BK=32 (2 k16 chunks), 8 warps (2x4), warp tile 64x32.
// smem row = 32 bf16 = 64B content, stride 80B (80/16=5 odd -> 8 rows cover all
// 8 16B bank groups; ldmatrix conflict-free).
#define BK       32
#define STRD2    80                        // bytes per bf16 smem row
#define SA_BYTES (128 * STRD2)             // 10240
#define SB_BYTES (128 * STRD2)             // 10240
#define STAGE_BYTES (SA_BYTES + SB_BYTES)  // 20480
#define STAGES   3
#define GEMM_SMEM (STAGES * STAGE_BYTES)   // 61440

template<bool RELU, bool BIAS, bool RESID, bool OUT16>
__device__ __forceinline__ void gemm_body(
    uint32_t sb,
    const __nv_bfloat16* __restrict__ A, const __nv_bfloat16* __restrict__ WT,
    const float* __restrict__ bias, const float* __restrict__ resid,
    void* __restrict__ Cv, int K, int M, int row0, int col0)
{
    const int tid  = threadIdx.x;
    const int wid  = tid >> 5;
    const int lane = tid & 31;
    const int warpM = wid & 1;
    const int warpN = wid >> 1;
    const int g = lane >> 2, t = lane & 3;

    const int laneRowA = ((lane >> 3) & 1) * 8 + (lane & 7);
    const int laneKA   = (lane >> 4) * 16;
    const int laneRowB = (lane >> 4) * 8 + (lane & 7);
    const int laneKB   = ((lane >> 3) & 1) * 16;

    float acc[4][4][4];
#pragma unroll
    for (int mt = 0; mt < 4; mt++)
#pragma unroll
        for (int nt = 0; nt < 4; nt++)
#pragma unroll
            for (int f = 0; f < 4; f++) acc[mt][nt][f] = 0.f;

    const int KT = K >> 5;

    auto copy_stage = [&](int kt, int st) {
        const int k0 = kt << 5;
        const uint32_t abase = sb + st * STAGE_BYTES;
        const uint32_t bbase = abase + SA_BYTES;
#pragma unroll
        for (int i = 0; i < 2; i++) {
            int c = tid + (i << 8);                // [0,512)
            int r = c >> 2, sgm = c & 3;           // 4x16B per 64B row
            cp_async16(abase + r * STRD2 + (sgm << 4),
                       &A[(size_t)(row0 + r) * K + k0 + (sgm << 3)]);
        }
#pragma unroll
        for (int i = 0; i < 2; i++) {
            int c = tid + (i << 8);
            int n = c >> 2, sgm = c & 3;
            cp_async16(bbase + n * STRD2 + (sgm << 4),
                       &WT[(size_t)(col0 + n) * K + k0 + (sgm << 3)]);
        }
    };

    copy_stage(0, 0); cp_commit();
    copy_stage(1, 1); cp_commit();

    for (int kt = 0; kt < KT; kt++) {
        const int st = kt % STAGES;
        cp_wait<1>();
        __syncthreads();
        if (kt + 2 < KT) copy_stage(kt + 2, (kt + 2) % STAGES);
        cp_commit();

        const uint32_t aB = sb + st * STAGE_BYTES
                          + (warpM * 64 + laneRowA) * STRD2 + laneKA;
        const uint32_t bB = sb + st * STAGE_BYTES + SA_BYTES
                          + (warpN * 32 + laneRowB) * STRD2 + laneKB;
#pragma unroll
        for (int kc = 0; kc < 2; kc++) {
            uint32_t a_[4][4], b_[4][2];
#pragma unroll
            for (int mt = 0; mt < 4; mt++)
                ldsm_x4(a_[mt][0], a_[mt][1], a_[mt][2], a_[mt][3],
                        aB + mt * 16 * STRD2 + (kc << 5));
#pragma unroll
            for (int p = 0; p < 2; p++)
                ldsm_x4(b_[2 * p][0], b_[2 * p][1], b_[2 * p + 1][0], b_[2 * p + 1][1],
                        bB + p * 16 * STRD2 + (kc << 5));
#pragma unroll
            for (int mt = 0; mt < 4; mt++)
#pragma unroll
                for (int nt = 0; nt < 4; nt++)
                    mma_bf16(acc[mt][nt], a_[mt], b_[nt]);
        }
    }

    float* Cf = (float*)Cv;
    __nv_bfloat16* Ch = (__nv_bfloat16*)Cv;
#pragma unroll
    for (int mt = 0; mt < 4; mt++) {
        int r_lo = row0 + warpM * 64 + mt * 16 + g;
        int r_hi = r_lo + 8;
#pragma unroll
        for (int nt = 0; nt < 4; nt++) {
            int col = col0 + warpN * 32 + nt * 8 + (t << 1);
            float2 v0 = make_float2(acc[mt][nt][0], acc[mt][nt][1]);
            float2 v1 = make_float2(acc[mt][nt][2], acc[mt][nt][3]);
            if (BIAS) {
                float2 bv = *(const float2*)&bias[col];
                v0.x += bv.x; v0.y += bv.y;
                v1.x += bv.x; v1.y += bv.y;
            }
            if (RESID) {
                float2 q0 = *(const float2*)&resid[(size_t)r_lo * M + col];
                float2 q1 = *(const float2*)&resid[(size_t)r_hi * M + col];
                v0.x += q0.x; v0.y += q0.y;
                v1.x += q1.x; v1.y += q1.y;
            }
            if (RELU) {
                v0.x = fmaxf(v0.x, 0.f); v0.y = fmaxf(v0.y, 0.f);
                v1.x = fmaxf(v1.x, 0.f); v1.y = fmaxf(v1.y, 0.f);
            }
            if (OUT16) {
                *(__nv_bfloat162*)&Ch[(size_t)r_lo * M + col] =
                    __floats2bfloat162_rn(v0.x, v0.y);
                *(__nv_bfloat162*)&Ch[(size_t)r_hi * M + col] =
                    __floats2bfloat162_rn(v1.x, v1.y);
            } else {
                *(float2*)&Cf[(size_t)r_lo * M + col] = v0;
                *(float2*)&Cf[(size_t)r_hi * M + col] = v1;
            }
        }
    }
}

template<bool RELU, bool BIAS, bool RESID, bool OUT16>
__global__ void __launch_bounds__(256, 2)
bf16_gemm_kernel(const __nv_bfloat16* __restrict__ A,
                 const __nv_bfloat16* __restrict__ WT,
                 const float* __restrict__ bias, const float* __restrict__ resid,
                 void* __restrict__ C, int K, int M)
{
    extern __shared__ char smem[];
    gemm_body<RELU, BIAS, RESID, OUT16>(smem_u32(smem), A, WT, bias, resid, C,
                                        K, M, blockIdx.x * 128, blockIdx.y * 128);
}

__global__ void __launch_bounds__(256, 2)
qkv_gemm_kernel(const __nv_bfloat16* __restrict__ A,
                const __nv_bfloat16* __restrict__ wqT,
                const __nv_bfloat16* __restrict__ wkT,
                const __nv_bfloat16* __restrict__ wvT,
                float* __restrict__ q, float* __restrict__ k, float* __restrict__ v)
{
    extern __shared__ char smem[];
    int y = blockIdx.y;
    int sel = y / 3;
    int col0 = (y - sel * 3) * 128;
    const __nv_bfloat16* WT = (sel == 0) ? wqT : (sel == 1) ? wkT : wvT;
    float* C = (sel == 0) ? q : (sel == 1) ? k : v;
    gemm_body<false, false, false, false>(smem_u32(smem), A, WT, nullptr, nullptr,
                                          C, DIM, DIM, blockIdx.x * 128, col0);
}

// ---------------- merged weight transpose -> bf16 (1 launch) ------------------
__global__ void transpose_all_kernel(
    const float* __restrict__ wq, const float* __restrict__ wk,
    const float* __restrict__ wv, const float* __restrict__ wo,
    const float* __restrict__ w1, const float* __restrict__ w2,
    __nv_bfloat16* __restrict__ wqT, __nv_bfloat16* __restrict__ wkT,
    __nv_bfloat16* __restrict__ wvT, __nv_bfloat16* __restrict__ woT,
    __nv_bfloat16* __restrict__ w1T, __nv_bfloat16* __restrict__ w2T)
{
    __shared__ float tbuf[32][33];
    int id = blockIdx.x;
    const float* in; __nv_bfloat16* out; int R, C, bx, by;
    if (id < 576) {
        int m = id / 144, r = id - m * 144;
        switch (m) {
            case 0: in = wq; out = wqT; break;
            case 1: in = wk; out = wkT; break;
            case 2: in = wv; out = wvT; break;
            default: in = wo; out = woT; break;
        }
        R = DIM; C = DIM; bx = (r % 12) * 32; by = (r / 12) * 32;
    } else if (id < 1152) {
        int r = id - 576;
        in = w1; out = w1T; R = DIM; C = FFDIM;
        bx = (r % 48) * 32; by = (r / 48) * 32;
    } else {
        int r = id - 1152;
        in = w2; out = w2T; R = FFDIM; C = DIM;
        bx = (r % 12) * 32; by = (r / 12) * 32;
    }
#pragma unroll
    for (int i = 0; i < 32; i += 8)
        tbuf[threadIdx.y + i][threadIdx.x] =
            in[(size_t)(by + threadIdx.y + i) * C + bx + threadIdx.x];
    __syncthreads();
#pragma unroll
    for (int i = 0; i < 32; i += 8)
        out[(size_t)(bx + threadIdx.y + i) * R + by + threadIdx.x] =
            __float2bfloat16_rn(tbuf[threadIdx.x][threadIdx.y + i]);
}

// ---------------- LayerNorm (float4 in, bf16 out) -----------------------------
__global__ void ln_kernel(const float* __restrict__ x,
                          const float* __restrict__ g,
                          const float* __restrict__ be,
                          __nv_bfloat16* __restrict__ out)
{
    int warp = (blockIdx.x * blockDim.x + threadIdx.x) >> 5;
    int lane = threadIdx.x & 31;
    if (warp >= NTOK) return;
    const float4* row = (const float4*)(x + (size_t)warp * DIM);
    float4 v[3];
    float s = 0.f, ss = 0.f;
#pragma unroll
    for (int i = 0; i < 3; i++) {
        v[i] = row[lane + 32 * i];
        s  += v[i].x + v[i].y + v[i].z + v[i].w;
        ss += v[i].x * v[i].x + v[i].y * v[i].y + v[i].z * v[i].z + v[i].w * v[i].w;
    }
#pragma unroll
    for (int o = 16; o; o >>= 1) {
        s  += __shfl_xor_sync(0xffffffffu, s, o);
        ss += __shfl_xor_sync(0xffffffffu, ss, o);
    }
    float mean = s * (1.0f / DIM);
    float var  = ss * (1.0f / DIM) - mean * mean;
    float rstd = rsqrtf(var + 1e-5f);
    __nv_bfloat16* orow = out + (size_t)warp * DIM;
#pragma unroll
    for (int i = 0; i < 3; i++) {
        int c4 = lane + 32 * i;
        float4 gv = *(const float4*)&g[c4 * 4];
        float4 bv = *(const float4*)&be[c4 * 4];
        float ox = (v[i].x - mean) * rstd * gv.x + bv.x;
        float oy = (v[i].y - mean) * rstd * gv.y + bv.y;
        float oz = (v[i].z - mean) * rstd * gv.z + bv.z;
        float ow = (v[i].w - mean) * rstd * gv.w + bv.w;
        *(__nv_bfloat162*)&orow[c4 * 4]     = __floats2bfloat162_rn(ox, oy);
        *(__nv_bfloat162*)&orow[c4 * 4 + 2] = __floats2bfloat162_rn(oz, ow);
    }
}

// ---------------- Tensor-core causal flash attention (tf32, bf16 out) ---------
#define AT_RS    68
#define AT_RB    (AT_RS * 4)               // 272
#define AT_VRB   (72 * 4)                  // 288
#define AT_KTILE (64 * AT_RB)              // 17408
#define AT_VTILE (64 * AT_VRB)             // 18432
#define AT_STAGE (AT_KTILE + AT_VTILE)     // 35840
#define ATTN_SMEM (2 * AT_STAGE)           // 71680

__global__ void __launch_bounds__(128, 3)
attn_mma_kernel(const float* __restrict__ q, const float* __restrict__ k,
                const float* __restrict__ v, __nv_bfloat16* __restrict__ ctx)
{
    extern __shared__ float sm[];
    const uint32_t sb = smem_u32(sm);

    const int qt = blockIdx.x;
    const int h  = blockIdx.y;
    const int b  = blockIdx.z;
    const int tid = threadIdx.x;
    const int wid = tid >> 5;
    const int lane = tid & 31;
    const int g = lane >> 2, t = lane & 3;
    const int w16 = wid * 16;

    const int laneRowA = ((lane >> 3) & 1) * 8 + (lane & 7);
    const int laneKA   = (lane >> 4) * 16;
    const int laneRowB = (lane >> 4) * 8 + (lane & 7);
    const int laneKB   = ((lane >> 3) & 1) * 16;

    const float* qbase = q + (size_t)b * SEQ * DIM + h * HDIM;
    const float* kbase = k + (size_t)b * SEQ * DIM + h * HDIM;
    const float* vbase = v + (size_t)b * SEQ * DIM + h * HDIM;

    auto stage_off = [&](int st) -> uint32_t {
        return st ? 0u : (uint32_t)AT_STAGE;
    };

#pragma unroll
    for (int i = 0; i < 8; i++) {
        int f = tid + (i << 7);
        int r = f >> 4, d4 = (f & 15) << 2;
        cp_async16(sb + r * AT_RB + (d4 << 2),
                   &qbase[(size_t)(qt * 64 + r) * DIM + d4]);
    }
    auto copy_kv = [&](int kt, int st) {
        const uint32_t kdst = sb + stage_off(st);
        const uint32_t vdst = kdst + AT_KTILE;
#pragma unroll
        for (int i = 0; i < 8; i++) {
            int f = tid + (i << 7);
            int r = f >> 4, d4 = (f & 15) << 2;
            cp_async16(kdst + r * AT_RB + (d4 << 2),
                       &kbase[(size_t)(kt * 64 + r) * DIM + d4]);
        }
#pragma unroll
        for (int i = 0; i < 8; i++) {
            int f = tid + (i << 7);
            int r = f >> 4, d4 = (f & 15) << 2;
            cp_async16(vdst + r * AT_VRB + (d4 << 2),
                       &vbase[(size_t)(kt * 64 + r) * DIM + d4]);
        }
    };

    copy_kv(0, 0);
    cp_commit();
    cp_wait<0>();
    __syncthreads();

    uint32_t qfrag[8][4];
    {
        const uint32_t aQ = sb + (w16 + laneRowA) * AT_RB + laneKA;
#pragma unroll
        for (int kc = 0; kc < 8; kc++)
            ldsm_x4(qfrag[kc][0], qfrag[kc][1], qfrag[kc][2], qfrag[kc][3],
                    aQ + (kc << 5));
    }
    __syncthreads();

    float m0 = -1e30f, m1 = -1e30f, l0 = 0.f, l1 = 0.f;
    float accO[8][4];
#pragma unroll
    for (int nt = 0; nt < 8; nt++)
#pragma unroll
        for (int f = 0; f < 4; f++) accO[nt][f] = 0.f;

    const int gq0 = qt * 64 + w16 + g;
    const int gq1 = gq0 + 8;
    const int src_lo = (lane & ~3) | (t >> 1);
    const int src_hi = src_lo + 2;

    const int KT = qt + 1;
    for (int kt = 0; kt < KT; kt++) {
        const int st = kt & 1;
        if (kt > 0) {
            cp_wait<0>();
            __syncthreads();
        }
        if (kt + 1 < KT) {
            copy_kv(kt + 1, st ^ 1);
            cp_commit();
        }

        float accS[8][4];
#pragma unroll
        for (int nt = 0; nt < 8; nt++)
#pragma unroll
            for (int f = 0; f < 4; f++) accS[nt][f] = 0.f;

        const uint32_t bK = sb + stage_off(st) + laneRowB * AT_RB + laneKB;
#pragma unroll
        for (int kc = 0; kc < 8; kc++) {
            uint32_t b_[8][2];
#pragma unroll
            for (int p = 0; p < 4; p++)
                ldsm_x4(b_[2 * p][0], b_[2 * p][1], b_[2 * p + 1][0], b_[2 * p + 1][1],
                        bK + p * 16 * AT_RB + (kc << 5));
#pragma unroll
            for (int nt = 0; nt < 8; nt++)
                mma_tf32(accS[nt], qfrag[kc], b_[nt]);
        }

#pragma unroll
        for (int nt = 0; nt < 8; nt++) {
            int gk = kt * 64 + nt * 8 + (t << 1);
            accS[nt][0] = (gk     > gq0) ? -1e30f : accS[nt][0] * 0.125f;
            accS[nt][1] = (gk + 1 > gq0) ? -1e30f : accS[nt][1] * 0.125f;
            accS[nt][2] = (gk     > gq1) ? -1e30f : accS[nt][2] * 0.125f;
            accS[nt][3] = (gk + 1 > gq1) ? -1e30f : accS[nt][3] * 0.125f;
        }

        float pm0 = -1e30f, pm1 = -1e30f;
#pragma unroll
        for (int nt = 0; nt < 8; nt++) {
            pm0 = fmaxf(pm0, fmaxf(accS[nt][0], accS[nt][1]));
            pm1 = fmaxf(pm1, fmaxf(accS[nt][2], accS[nt][3]));
        }
        pm0 = fmaxf(pm0, __shfl_xor_sync(0xffffffffu, pm0, 1));
        pm0 = fmaxf(pm0, __shfl_xor_sync(0xffffffffu, pm0, 2));
        pm1 = fmaxf(pm1, __shfl_xor_sync(0xffffffffu, pm1, 1));
        pm1 = fmaxf(pm1, __shfl_xor_sync(0xffffffffu, pm1, 2));
        float mn0 = fmaxf(m0, pm0), mn1 = fmaxf(m1, pm1);
        float al0 = __expf(m0 - mn0), al1 = __expf(m1 - mn1);
        m0 = mn0; m1 = mn1;
        float sum0 = 0.f, sum1 = 0.f;
#pragma unroll
        for (int nt = 0; nt < 8; nt++) {
            accS[nt][0] = __expf(accS[nt][0] - mn0);
            accS[nt][1] = __expf(accS[nt][1] - mn0);
            accS[nt][2] = __expf(accS[nt][2] - mn1);
            accS[nt][3] = __expf(accS[nt][3] - mn1);
            sum0 += accS[nt][0] + accS[nt][1];
            sum1 += accS[nt][2] + accS[nt][3];
        }
        sum0 += __shfl_xor_sync(0xffffffffu, sum0, 1);
        sum0 += __shfl_xor_sync(0xffffffffu, sum0, 2);
        sum1 += __shfl_xor_sync(0xffffffffu, sum1, 1);
        sum1 += __shfl_xor_sync(0xffffffffu, sum1, 2);
        l0 = l0 * al0 + sum0;
        l1 = l1 * al1 + sum1;

#pragma unroll
        for (int nt = 0; nt < 8; nt++) {
            accO[nt][0] *= al0; accO[nt][1] *= al0;
            accO[nt][2] *= al1; accO[nt][3] *= al1;
        }
        const uint32_t bV = sb + stage_off(st) + AT_KTILE
                          + t * AT_VRB + (g << 2);
#pragma unroll
        for (int kc = 0; kc < 8; kc++) {
            float x0 = __shfl_sync(0xffffffffu, accS[kc][0], src_lo);
            float x1 = __shfl_sync(0xffffffffu, accS[kc][1], src_lo);
            float y0 = __shfl_sync(0xffffffffu, accS[kc][0], src_hi);
            float y1 = __shfl_sync(0xffffffffu, accS[kc][1], src_hi);
            float z0 = __shfl_sync(0xffffffffu, accS[kc][2], src_lo);
            float z1 = __shfl_sync(0xffffffffu, accS[kc][3], src_lo);
            float u0 = __shfl_sync(0xffffffffu, accS[kc][2], src_hi);
            float u1 = __shfl_sync(0xffffffffu, accS[kc][3], src_hi);
            uint32_t a_[4];
            a_[0] = __float_as_uint((t & 1) ? x1 : x0);
            a_[1] = __float_as_uint((t & 1) ? z1 : z0);
            a_[2] = __float_as_uint((t & 1) ? y1 : y0);
            a_[3] = __float_as_uint((t & 1) ? u1 : u0);
#pragma unroll
            for (int nt = 0; nt < 8; nt++) {
                uint32_t b_[2];
                uint32_t ba = bV + kc * 8 * AT_VRB + (nt << 5);
                b_[0] = lds32(ba);
                b_[1] = lds32(ba + 4 * AT_VRB);
                mma_tf32(accO[nt], a_, b_);
            }
        }
    }

    // write ctx (bf16) = O / l
    {
        const int r0 = w16 + g, r1 = r0 + 8;
        float inv0 = 1.0f / l0;
        float inv1 = 1.0f / l1;
        __nv_bfloat16* obase = ctx + (size_t)b * SEQ * DIM + h * HDIM;
        __nv_bfloat16* o0 = &obase[(size_t)(qt * 64 + r0) * DIM];
        __nv_bfloat16* o1 = &obase[(size_t)(qt * 64 + r1) * DIM];
#pragma unroll
        for (int nt = 0; nt < 8; nt++) {
            int c = nt * 8 + (t << 1);
            *(__nv_bfloat162*)&o0[c] =
                __floats2bfloat162_rn(accO[nt][0] * inv0, accO[nt][1] * inv0);
            *(__nv_bfloat162*)&o1[c] =
                __floats2bfloat162_rn(accO[nt][2] * inv1, accO[nt][3] * inv1);
        }
    }
}

// ---------------- launch ------------------------------------------------------
template<typename T>
static T* dev_ptr_t(const void* sym)
{
    void* p = nullptr;
    cudaGetSymbolAddress(&p, sym);
    return (T*)p;
}

extern "C" void kernel_launch(void* const* d_in, const int* in_sizes, int n_in,
                              void* d_out, int out_size)
{
    (void)in_sizes; (void)n_in; (void)out_size;
    const float* x   = (const float*)d_in[0];
    const float* wq  = (const float*)d_in[1];
    const float* wk  = (const float*)d_in[2];
    const float* wv  = (const float*)d_in[3];
    const float* wo  = (const float*)d_in[4];
    const float* bo  = (const float*)d_in[5];
    const float* w1  = (const float*)d_in[6];
    const float* b1  = (const float*)d_in[7];
    const float* w2  = (const float*)d_in[8];
    const float* b2  = (const float*)d_in[9];
    const float* g1  = (const float*)d_in[10];
    const float* be1 = (const float*)d_in[11];
    const float* g2  = (const float*)d_in[12];
    const float* be2 = (const float*)d_in[13];
    float* out = (float*)d_out;

    __nv_bfloat16* hb  = dev_ptr_t<__nv_bfloat16>(g_hb);
    float* qb          = dev_ptr_t<float>(g_q);
    float* kb          = dev_ptr_t<float>(g_k);
    float* vb          = dev_ptr_t<float>(g_v);
    __nv_bfloat16* ctxb = dev_ptr_t<__nv_bfloat16>(g_ctxb);
    float* x1          = dev_ptr_t<float>(g_x1);
    __nv_bfloat16* ffb = dev_ptr_t<__nv_bfloat16>(g_ffb);
    __nv_bfloat16* wqT = dev_ptr_t<__nv_bfloat16>(g_wqT);
    __nv_bfloat16* wkT = dev_ptr_t<__nv_bfloat16>(g_wkT);
    __nv_bfloat16* wvT = dev_ptr_t<__nv_bfloat16>(g_wvT);
    __nv_bfloat16* woT = dev_ptr_t<__nv_bfloat16>(g_woT);
    __nv_bfloat16* w1T = dev_ptr_t<__nv_bfloat16>(g_w1T);
    __nv_bfloat16* w2T = dev_ptr_t<__nv_bfloat16>(g_w2T);

    cudaFuncSetAttribute(attn_mma_kernel, cudaFuncAttributeMaxDynamicSharedMemorySize, ATTN_SMEM);
    cudaFuncSetAttribute(qkv_gemm_kernel,
                         cudaFuncAttributeMaxDynamicSharedMemorySize, GEMM_SMEM);
    cudaFuncSetAttribute(bf16_gemm_kernel<false, true, true, false>,
                         cudaFuncAttributeMaxDynamicSharedMemorySize, GEMM_SMEM);
    cudaFuncSetAttribute(bf16_gemm_kernel<true, true, false, true>,
                         cudaFuncAttributeMaxDynamicSharedMemorySize, GEMM_SMEM);

    // weight transposes + fp32->bf16 (one launch)
    transpose_all_kernel<<<1728, dim3(32, 8)>>>(wq, wk, wv, wo, w1, w2,
                                                wqT, wkT, wvT, woT, w1T, w2T);
    // LN1 -> bf16 h
    ln_kernel<<<NTOK / 8, 256>>>(x, g1, be1, hb);
    // fused QKV projections (bf16 mma, fp32 out)
    qkv_gemm_kernel<<<dim3(NTOK / 128, 9), 256, GEMM_SMEM>>>(hb, wqT, wkT, wvT, qb, kb, vb);
    // attention (tf32 mma, bf16 ctx out)
    attn_mma_kernel<<<dim3(SEQ / 64, NHEAD, BATCH), 128, ATTN_SMEM>>>(qb, kb, vb, ctxb);
    // output projection + residual (fp32 out)
    bf16_gemm_kernel<false, true, true, false><<<dim3(NTOK / 128, 3), 256, GEMM_SMEM>>>(
        ctxb, woT, bo, x, x1, DIM, DIM);
    // LN2 -> bf16 h
    ln_kernel<<<NTOK / 8, 256>>>(x1, g2, be2, hb);
    // FFN1 (ReLU, bf16 out)
    bf16_gemm_kernel<true, true, false, true><<<dim3(NTOK / 128, 12), 256, GEMM_SMEM>>>(
        hb, w1T, b1, nullptr, ffb, DIM, FFDIM);
    // FFN2 (+residual, fp32 out)
    bf16_gemm_kernel<false, true, true, false><<<dim3(NTOK / 128, 3), 256, GEMM_SMEM>>>(
        ffb, w2T, b2, x1, out, FFDIM, DIM);
}

// round 13
// speedup vs baseline: 2.0605x; 1.0423x over previous
#include <cuda_runtime.h>
#include <cuda_bf16.h>
#include <cstdint>
#include <math.h>

// Problem dims
#define BATCH 64
#define SEQ   256
#define DIM   384
#define NHEAD 6
#define HDIM  64
#define NTOK  (BATCH * SEQ)      // 16384
#define FFDIM (4 * DIM)          // 1536

// ---------------- scratch (static device globals; no allocation) -------------
__device__ __nv_bfloat16 g_hb [NTOK * DIM];
__device__ float         g_q  [NTOK * DIM];
__device__ float         g_k  [NTOK * DIM];
__device__ float         g_v  [NTOK * DIM];
__device__ __nv_bfloat16 g_ctxb[NTOK * DIM];
__device__ float         g_x1 [NTOK * DIM];
__device__ __nv_bfloat16 g_ffb[NTOK * FFDIM];
__device__ __nv_bfloat16 g_wqT[DIM * DIM];
__device__ __nv_bfloat16 g_wkT[DIM * DIM];
__device__ __nv_bfloat16 g_wvT[DIM * DIM];
__device__ __nv_bfloat16 g_woT[DIM * DIM];
__device__ __nv_bfloat16 g_w1T[DIM * FFDIM];
__device__ __nv_bfloat16 g_w2T[FFDIM * DIM];

// ---------------- PTX helpers -------------------------------------------------
__device__ __forceinline__ uint32_t smem_u32(const void* p) {
    uint32_t a;
    asm("{ .reg .u64 t; cvta.to.shared.u64 t, %1; cvt.u32.u64 %0, t; }"
        : "=r"(a) : "l"(p));
    return a;
}
__device__ __forceinline__ void cp_async16(uint32_t dst, const void* src) {
    asm volatile("cp.async.cg.shared.global [%0], [%1], 16;" :: "r"(dst), "l"(src));
}
__device__ __forceinline__ void cp_commit() {
    asm volatile("cp.async.commit_group;" ::: "memory");
}
template<int N> __device__ __forceinline__ void cp_wait() {
    asm volatile("cp.async.wait_group %0;" :: "n"(N) : "memory");
}
__device__ __forceinline__ void mma_tf32(float* c, const uint32_t* a, const uint32_t* b) {
    asm volatile(
        "mma.sync.aligned.m16n8k8.row.col.f32.tf32.tf32.f32 "
        "{%0,%1,%2,%3}, {%4,%5,%6,%7}, {%8,%9}, {%0,%1,%2,%3};"
        : "+f"(c[0]), "+f"(c[1]), "+f"(c[2]), "+f"(c[3])
        : "r"(a[0]), "r"(a[1]), "r"(a[2]), "r"(a[3]), "r"(b[0]), "r"(b[1]));
}
__device__ __forceinline__ void mma_bf16(float* c, const uint32_t* a, const uint32_t* b) {
    asm volatile(
        "mma.sync.aligned.m16n8k16.row.col.f32.bf16.bf16.f32 "
        "{%0,%1,%2,%3}, {%4,%5,%6,%7}, {%8,%9}, {%0,%1,%2,%3};"
        : "+f"(c[0]), "+f"(c[1]), "+f"(c[2]), "+f"(c[3])
        : "r"(a[0]), "r"(a[1]), "r"(a[2]), "r"(a[3]), "r"(b[0]), "r"(b[1]));
}
__device__ __forceinline__ void ldsm_x4(uint32_t& r0, uint32_t& r1, uint32_t& r2,
                                        uint32_t& r3, uint32_t addr) {
    asm volatile("ldmatrix.sync.aligned.m8n8.x4.shared.b16 {%0,%1,%2,%3}, [%4];"
                 : "=r"(r0), "=r"(r1), "=r"(r2), "=r"(r3) : "r"(addr));
}
__device__ __forceinline__ uint32_t lds32(uint32_t addr) {
    uint32_t v;
    asm volatile("ld.shared.b32 %0, [%1];" : "=r"(v) : "r"(addr));
    return v;
}

// ================= bf16 mma.sync GEMM, BK=64, cp.async 3-stage ===============
// A: [N,K] bf16 row-major, WT: [M,K] bf16 row-major, C = act(A@W+bias+resid).
// CTA 128x128, BK=64 (4 k16 chunks), 8 warps (2x4), warp tile 64x32.
// smem row = 64 bf16 = 128B content, stride 144B (144/16=9 odd -> ldmatrix
// conflict-free across all 8 16B bank groups).
#define BK       64
#define STRD2    144                       // bytes per bf16 smem row
#define SA_BYTES (128 * STRD2)             // 18432
#define SB_BYTES (128 * STRD2)             // 18432
#define STAGE_BYTES (SA_BYTES + SB_BYTES)  // 36864
#define STAGES   3
#define GEMM_SMEM (STAGES * STAGE_BYTES)   // 110592

template<bool RELU, bool BIAS, bool RESID, bool OUT16>
__device__ __forceinline__ void gemm_body(
    uint32_t sb,
    const __nv_bfloat16* __restrict__ A, const __nv_bfloat16* __restrict__ WT,
    const float* __restrict__ bias, const float* __restrict__ resid,
    void* __restrict__ Cv, int K, int M, int row0, int col0, float cscale)
{
    const int tid  = threadIdx.x;
    const int wid  = tid >> 5;
    const int lane = tid & 31;
    const int warpM = wid & 1;
    const int warpN = wid >> 1;
    const int g = lane >> 2, t = lane & 3;

    const int laneRowA = ((lane >> 3) & 1) * 8 + (lane & 7);
    const int laneKA   = (lane >> 4) * 16;
    const int laneRowB = (lane >> 4) * 8 + (lane & 7);
    const int laneKB   = ((lane >> 3) & 1) * 16;

    float acc[4][4][4];
#pragma unroll
    for (int mt = 0; mt < 4; mt++)
#pragma unroll
        for (int nt = 0; nt < 4; nt++)
#pragma unroll
            for (int f = 0; f < 4; f++) acc[mt][nt][f] = 0.f;

    const int KT = K >> 6;

    auto copy_stage = [&](int kt, int st) {
        const int k0 = kt << 6;
        const uint32_t abase = sb + st * STAGE_BYTES;
        const uint32_t bbase = abase + SA_BYTES;
#pragma unroll
        for (int i = 0; i < 4; i++) {
            int c = tid + (i << 8);                // [0,1024)
            int r = c >> 3, sgm = c & 7;           // 8x16B per 128B row
            cp_async16(abase + r * STRD2 + (sgm << 4),
                       &A[(size_t)(row0 + r) * K + k0 + (sgm << 3)]);
        }
#pragma unroll
        for (int i = 0; i < 4; i++) {
            int c = tid + (i << 8);
            int n = c >> 3, sgm = c & 7;
            cp_async16(bbase + n * STRD2 + (sgm << 4),
                       &WT[(size_t)(col0 + n) * K + k0 + (sgm << 3)]);
        }
    };

    copy_stage(0, 0); cp_commit();
    copy_stage(1, 1); cp_commit();

    for (int kt = 0; kt < KT; kt++) {
        const int st = kt % STAGES;
        cp_wait<1>();
        __syncthreads();
        if (kt + 2 < KT) copy_stage(kt + 2, (kt + 2) % STAGES);
        cp_commit();

        const uint32_t aB = sb + st * STAGE_BYTES
                          + (warpM * 64 + laneRowA) * STRD2 + laneKA;
        const uint32_t bB = sb + st * STAGE_BYTES + SA_BYTES
                          + (warpN * 32 + laneRowB) * STRD2 + laneKB;
#pragma unroll
        for (int kc = 0; kc < 4; kc++) {
            uint32_t a_[4][4], b_[4][2];
#pragma unroll
            for (int mt = 0; mt < 4; mt++)
                ldsm_x4(a_[mt][0], a_[mt][1], a_[mt][2], a_[mt][3],
                        aB + mt * 16 * STRD2 + (kc << 5));
#pragma unroll
            for (int p = 0; p < 2; p++)
                ldsm_x4(b_[2 * p][0], b_[2 * p][1], b_[2 * p + 1][0], b_[2 * p + 1][1],
                        bB + p * 16 * STRD2 + (kc << 5));
#pragma unroll
            for (int mt = 0; mt < 4; mt++)
#pragma unroll
                for (int nt = 0; nt < 4; nt++)
                    mma_bf16(acc[mt][nt], a_[mt], b_[nt]);
        }
    }

    float* Cf = (float*)Cv;
    __nv_bfloat16* Ch = (__nv_bfloat16*)Cv;
#pragma unroll
    for (int mt = 0; mt < 4; mt++) {
        int r_lo = row0 + warpM * 64 + mt * 16 + g;
        int r_hi = r_lo + 8;
#pragma unroll
        for (int nt = 0; nt < 4; nt++) {
            int col = col0 + warpN * 32 + nt * 8 + (t << 1);
            float2 v0 = make_float2(acc[mt][nt][0] * cscale, acc[mt][nt][1] * cscale);
            float2 v1 = make_float2(acc[mt][nt][2] * cscale, acc[mt][nt][3] * cscale);
            if (BIAS) {
                float2 bv = *(const float2*)&bias[col];
                v0.x += bv.x; v0.y += bv.y;
                v1.x += bv.x; v1.y += bv.y;
            }
            if (RESID) {
                float2 q0 = *(const float2*)&resid[(size_t)r_lo * M + col];
                float2 q1 = *(const float2*)&resid[(size_t)r_hi * M + col];
                v0.x += q0.x; v0.y += q0.y;
                v1.x += q1.x; v1.y += q1.y;
            }
            if (RELU) {
                v0.x = fmaxf(v0.x, 0.f); v0.y = fmaxf(v0.y, 0.f);
                v1.x = fmaxf(v1.x, 0.f); v1.y = fmaxf(v1.y, 0.f);
            }
            if (OUT16) {
                *(__nv_bfloat162*)&Ch[(size_t)r_lo * M + col] =
                    __floats2bfloat162_rn(v0.x, v0.y);
                *(__nv_bfloat162*)&Ch[(size_t)r_hi * M + col] =
                    __floats2bfloat162_rn(v1.x, v1.y);
            } else {
                *(float2*)&Cf[(size_t)r_lo * M + col] = v0;
                *(float2*)&Cf[(size_t)r_hi * M + col] = v1;
            }
        }
    }
}

template<bool RELU, bool BIAS, bool RESID, bool OUT16>
__global__ void __launch_bounds__(256, 2)
bf16_gemm_kernel(const __nv_bfloat16* __restrict__ A,
                 const __nv_bfloat16* __restrict__ WT,
                 const float* __restrict__ bias, const float* __restrict__ resid,
                 void* __restrict__ C, int K, int M)
{
    extern __shared__ char smem[];
    gemm_body<RELU, BIAS, RESID, OUT16>(smem_u32(smem), A, WT, bias, resid, C,
                                        K, M, blockIdx.x * 128, blockIdx.y * 128,
                                        1.0f);
}

// Fused QKV; Q outputs pre-scaled by 1/sqrt(HDIM)=0.125 (exact power of two).
__global__ void __launch_bounds__(256, 2)
qkv_gemm_kernel(const __nv_bfloat16* __restrict__ A,
                const __nv_bfloat16* __restrict__ wqT,
                const __nv_bfloat16* __restrict__ wkT,
                const __nv_bfloat16* __restrict__ wvT,
                float* __restrict__ q, float* __restrict__ k, float* __restrict__ v)
{
    extern __shared__ char smem[];
    int y = blockIdx.y;
    int sel = y / 3;
    int col0 = (y - sel * 3) * 128;
    const __nv_bfloat16* WT = (sel == 0) ? wqT : (sel == 1) ? wkT : wvT;
    float* C = (sel == 0) ? q : (sel == 1) ? k : v;
    float cscale = (sel == 0) ? 0.125f : 1.0f;
    gemm_body<false, false, false, false>(smem_u32(smem), A, WT, nullptr, nullptr,
                                          C, DIM, DIM, blockIdx.x * 128, col0,
                                          cscale);
}

// ---------------- merged weight transpose -> bf16 (1 launch) ------------------
__global__ void transpose_all_kernel(
    const float* __restrict__ wq, const float* __restrict__ wk,
    const float* __restrict__ wv, const float* __restrict__ wo,
    const float* __restrict__ w1, const float* __restrict__ w2,
    __nv_bfloat16* __restrict__ wqT, __nv_bfloat16* __restrict__ wkT,
    __nv_bfloat16* __restrict__ wvT, __nv_bfloat16* __restrict__ woT,
    __nv_bfloat16* __restrict__ w1T, __nv_bfloat16* __restrict__ w2T)
{
    __shared__ float tbuf[32][33];
    int id = blockIdx.x;
    const float* in; __nv_bfloat16* out; int R, C, bx, by;
    if (id < 576) {
        int m = id / 144, r = id - m * 144;
        switch (m) {
            case 0: in = wq; out = wqT; break;
            case 1: in = wk; out = wkT; break;
            case 2: in = wv; out = wvT; break;
            default: in = wo; out = woT; break;
        }
        R = DIM; C = DIM; bx = (r % 12) * 32; by = (r / 12) * 32;
    } else if (id < 1152) {
        int r = id - 576;
        in = w1; out = w1T; R = DIM; C = FFDIM;
        bx = (r % 48) * 32; by = (r / 48) * 32;
    } else {
        int r = id - 1152;
        in = w2; out = w2T; R = FFDIM; C = DIM;
        bx = (r % 12) * 32; by = (r / 12) * 32;
    }
#pragma unroll
    for (int i = 0; i < 32; i += 8)
        tbuf[threadIdx.y + i][threadIdx.x] =
            in[(size_t)(by + threadIdx.y + i) * C + bx + threadIdx.x];
    __syncthreads();
#pragma unroll
    for (int i = 0; i < 32; i += 8)
        out[(size_t)(bx + threadIdx.y + i) * R + by + threadIdx.x] =
            __float2bfloat16_rn(tbuf[threadIdx.x][threadIdx.y + i]);
}

// ---------------- LayerNorm (float4 in, bf16 out) -----------------------------
__global__ void ln_kernel(const float* __restrict__ x,
                          const float* __restrict__ g,
                          const float* __restrict__ be,
                          __nv_bfloat16* __restrict__ out)
{
    int warp = (blockIdx.x * blockDim.x + threadIdx.x) >> 5;
    int lane = threadIdx.x & 31;
    if (warp >= NTOK) return;
    const float4* row = (const float4*)(x + (size_t)warp * DIM);
    float4 v[3];
    float s = 0.f, ss = 0.f;
#pragma unroll
    for (int i = 0; i < 3; i++) {
        v[i] = row[lane + 32 * i];
        s  += v[i].x + v[i].y + v[i].z + v[i].w;
        ss += v[i].x * v[i].x + v[i].y * v[i].y + v[i].z * v[i].z + v[i].w * v[i].w;
    }
#pragma unroll
    for (int o = 16; o; o >>= 1) {
        s  += __shfl_xor_sync(0xffffffffu, s, o);
        ss += __shfl_xor_sync(0xffffffffu, ss, o);
    }
    float mean = s * (1.0f / DIM);
    float var  = ss * (1.0f / DIM) - mean * mean;
    float rstd = rsqrtf(var + 1e-5f);
    __nv_bfloat16* orow = out + (size_t)warp * DIM;
#pragma unroll
    for (int i = 0; i < 3; i++) {
        int c4 = lane + 32 * i;
        float4 gv = *(const float4*)&g[c4 * 4];
        float4 bv = *(const float4*)&be[c4 * 4];
        float ox = (v[i].x - mean) * rstd * gv.x + bv.x;
        float oy = (v[i].y - mean) * rstd * gv.y + bv.y;
        float oz = (v[i].z - mean) * rstd * gv.z + bv.z;
        float ow = (v[i].w - mean) * rstd * gv.w + bv.w;
        *(__nv_bfloat162*)&orow[c4 * 4]     = __floats2bfloat162_rn(ox, oy);
        *(__nv_bfloat162*)&orow[c4 * 4 + 2] = __floats2bfloat162_rn(oz, ow);
    }
}

// ---------------- Tensor-core causal flash attention (tf32, bf16 out) ---------
// Q comes pre-scaled by 0.125 from the QKV GEMM. Mask applied ONLY on the
// diagonal k-tile (kt == qt); interior tiles have no masked elements.
#define AT_RS    68
#define AT_RB    (AT_RS * 4)               // 272
#define AT_VRB   (72 * 4)                  // 288
#define AT_KTILE (64 * AT_RB)              // 17408
#define AT_VTILE (64 * AT_VRB)             // 18432
#define AT_STAGE (AT_KTILE + AT_VTILE)     // 35840
#define ATTN_SMEM (2 * AT_STAGE)           // 71680

__global__ void __launch_bounds__(128, 3)
attn_mma_kernel(const float* __restrict__ q, const float* __restrict__ k,
                const float* __restrict__ v, __nv_bfloat16* __restrict__ ctx)
{
    extern __shared__ float sm[];
    const uint32_t sb = smem_u32(sm);

    const int qt = blockIdx.x;
    const int h  = blockIdx.y;
    const int b  = blockIdx.z;
    const int tid = threadIdx.x;
    const int wid = tid >> 5;
    const int lane = tid & 31;
    const int g = lane >> 2, t = lane & 3;
    const int w16 = wid * 16;

    const int laneRowA = ((lane >> 3) & 1) * 8 + (lane & 7);
    const int laneKA   = (lane >> 4) * 16;
    const int laneRowB = (lane >> 4) * 8 + (lane & 7);
    const int laneKB   = ((lane >> 3) & 1) * 16;

    const float* qbase = q + (size_t)b * SEQ * DIM + h * HDIM;
    const float* kbase = k + (size_t)b * SEQ * DIM + h * HDIM;
    const float* vbase = v + (size_t)b * SEQ * DIM + h * HDIM;

    auto stage_off = [&](int st) -> uint32_t {
        return st ? 0u : (uint32_t)AT_STAGE;
    };

#pragma unroll
    for (int i = 0; i < 8; i++) {
        int f = tid + (i << 7);
        int r = f >> 4, d4 = (f & 15) << 2;
        cp_async16(sb + r * AT_RB + (d4 << 2),
                   &qbase[(size_t)(qt * 64 + r) * DIM + d4]);
    }
    auto copy_kv = [&](int kt, int st) {
        const uint32_t kdst = sb + stage_off(st);
        const uint32_t vdst = kdst + AT_KTILE;
#pragma unroll
        for (int i = 0; i < 8; i++) {
            int f = tid + (i << 7);
            int r = f >> 4, d4 = (f & 15) << 2;
            cp_async16(kdst + r * AT_RB + (d4 << 2),
                       &kbase[(size_t)(kt * 64 + r) * DIM + d4]);
        }
#pragma unroll
        for (int i = 0; i < 8; i++) {
            int f = tid + (i << 7);
            int r = f >> 4, d4 = (f & 15) << 2;
            cp_async16(vdst + r * AT_VRB + (d4 << 2),
                       &vbase[(size_t)(kt * 64 + r) * DIM + d4]);
        }
    };

    copy_kv(0, 0);
    cp_commit();
    cp_wait<0>();
    __syncthreads();

    uint32_t qfrag[8][4];
    {
        const uint32_t aQ = sb + (w16 + laneRowA) * AT_RB + laneKA;
#pragma unroll
        for (int kc = 0; kc < 8; kc++)
            ldsm_x4(qfrag[kc][0], qfrag[kc][1], qfrag[kc][2], qfrag[kc][3],
                    aQ + (kc << 5));
    }
    __syncthreads();

    float m0 = -1e30f, m1 = -1e30f, l0 = 0.f, l1 = 0.f;
    float accO[8][4];
#pragma unroll
    for (int nt = 0; nt < 8; nt++)
#pragma unroll
        for (int f = 0; f < 4; f++) accO[nt][f] = 0.f;

    const int r0loc = w16 + g;          // local row (0..63)
    const int src_lo = (lane & ~3) | (t >> 1);
    const int src_hi = src_lo + 2;

    const int KT = qt + 1;
    for (int kt = 0; kt < KT; kt++) {
        const int st = kt & 1;
        if (kt > 0) {
            cp_wait<0>();
            __syncthreads();
        }
        if (kt + 1 < KT) {
            copy_kv(kt + 1, st ^ 1);
            cp_commit();
        }

        float accS[8][4];
#pragma unroll
        for (int nt = 0; nt < 8; nt++)
#pragma unroll
            for (int f = 0; f < 4; f++) accS[nt][f] = 0.f;

        const uint32_t bK = sb + stage_off(st) + laneRowB * AT_RB + laneKB;
#pragma unroll
        for (int kc = 0; kc < 8; kc++) {
            uint32_t b_[8][2];
#pragma unroll
            for (int p = 0; p < 4; p++)
                ldsm_x4(b_[2 * p][0], b_[2 * p][1], b_[2 * p + 1][0], b_[2 * p + 1][1],
                        bK + p * 16 * AT_RB + (kc << 5));
#pragma unroll
            for (int nt = 0; nt < 8; nt++)
                mma_tf32(accS[nt], qfrag[kc], b_[nt]);
        }

        // mask only on the diagonal tile (Q pre-scaled; no per-element scale)
        if (kt == qt) {
#pragma unroll
            for (int nt = 0; nt < 8; nt++) {
                int c = nt * 8 + (t << 1);           // local key col
                accS[nt][0] = (c     > r0loc)     ? -1e30f : accS[nt][0];
                accS[nt][1] = (c + 1 > r0loc)     ? -1e30f : accS[nt][1];
                accS[nt][2] = (c     > r0loc + 8) ? -1e30f : accS[nt][2];
                accS[nt][3] = (c + 1 > r0loc + 8) ? -1e30f : accS[nt][3];
            }
        }

        float pm0 = -1e30f, pm1 = -1e30f;
#pragma unroll
        for (int nt = 0; nt < 8; nt++) {
            pm0 = fmaxf(pm0, fmaxf(accS[nt][0], accS[nt][1]));
            pm1 = fmaxf(pm1, fmaxf(accS[nt][2], accS[nt][3]));
        }
        pm0 = fmaxf(pm0, __shfl_xor_sync(0xffffffffu, pm0, 1));
        pm0 = fmaxf(pm0, __shfl_xor_sync(0xffffffffu, pm0, 2));
        pm1 = fmaxf(pm1, __shfl_xor_sync(0xffffffffu, pm1, 1));
        pm1 = fmaxf(pm1, __shfl_xor_sync(0xffffffffu, pm1, 2));
        float mn0 = fmaxf(m0, pm0), mn1 = fmaxf(m1, pm1);
        float al0 = __expf(m0 - mn0), al1 = __expf(m1 - mn1);
        m0 = mn0; m1 = mn1;
        float sum0 = 0.f, sum1 = 0.f;
#pragma unroll
        for (int nt = 0; nt < 8; nt++) {
            accS[nt][0] = __expf(accS[nt][0] - mn0);
            accS[nt][1] = __expf(accS[nt][1] - mn0);
            accS[nt][2] = __expf(accS[nt][2] - mn1);
            accS[nt][3] = __expf(accS[nt][3] - mn1);
            sum0 += accS[nt][0] + accS[nt][1];
            sum1 += accS[nt][2] + accS[nt][3];
        }
        sum0 += __shfl_xor_sync(0xffffffffu, sum0, 1);
        sum0 += __shfl_xor_sync(0xffffffffu, sum0, 2);
        sum1 += __shfl_xor_sync(0xffffffffu, sum1, 1);
        sum1 += __shfl_xor_sync(0xffffffffu, sum1, 2);
        l0 = l0 * al0 + sum0;
        l1 = l1 * al1 + sum1;

#pragma unroll
        for (int nt = 0; nt < 8; nt++) {
            accO[nt][0] *= al0; accO[nt][1] *= al0;
            accO[nt][2] *= al1; accO[nt][3] *= al1;
        }
        const uint32_t bV = sb + stage_off(st) + AT_KTILE
                          + t * AT_VRB + (g << 2);
#pragma unroll
        for (int kc = 0; kc < 8; kc++) {
            float x0 = __shfl_sync(0xffffffffu, accS[kc][0], src_lo);
            float x1 = __shfl_sync(0xffffffffu, accS[kc][1], src_lo);
            float y0 = __shfl_sync(0xffffffffu, accS[kc][0], src_hi);
            float y1 = __shfl_sync(0xffffffffu, accS[kc][1], src_hi);
            float z0 = __shfl_sync(0xffffffffu, accS[kc][2], src_lo);
            float z1 = __shfl_sync(0xffffffffu, accS[kc][3], src_lo);
            float u0 = __shfl_sync(0xffffffffu, accS[kc][2], src_hi);
            float u1 = __shfl_sync(0xffffffffu, accS[kc][3], src_hi);
            uint32_t a_[4];
            a_[0] = __float_as_uint((t & 1) ? x1 : x0);
            a_[1] = __float_as_uint((t & 1) ? z1 : z0);
            a_[2] = __float_as_uint((t & 1) ? y1 : y0);
            a_[3] = __float_as_uint((t & 1) ? u1 : u0);
#pragma unroll
            for (int nt = 0; nt < 8; nt++) {
                uint32_t b_[2];
                uint32_t ba = bV + kc * 8 * AT_VRB + (nt << 5);
                b_[0] = lds32(ba);
                b_[1] = lds32(ba + 4 * AT_VRB);
                mma_tf32(accO[nt], a_, b_);
            }
        }
    }

    {
        const int r0 = w16 + g, r1 = r0 + 8;
        float inv0 = 1.0f / l0;
        float inv1 = 1.0f / l1;
        __nv_bfloat16* obase = ctx + (size_t)b * SEQ * DIM + h * HDIM;
        __nv_bfloat16* o0 = &obase[(size_t)(qt * 64 + r0) * DIM];
        __nv_bfloat16* o1 = &obase[(size_t)(qt * 64 + r1) * DIM];
#pragma unroll
        for (int nt = 0; nt < 8; nt++) {
            int c = nt * 8 + (t << 1);
            *(__nv_bfloat162*)&o0[c] =
                __floats2bfloat162_rn(accO[nt][0] * inv0, accO[nt][1] * inv0);
            *(__nv_bfloat162*)&o1[c] =
                __floats2bfloat162_rn(accO[nt][2] * inv1, accO[nt][3] * inv1);
        }
    }
}

// ---------------- launch ------------------------------------------------------
template<typename T>
static T* dev_ptr_t(const void* sym)
{
    void* p = nullptr;
    cudaGetSymbolAddress(&p, sym);
    return (T*)p;
}

extern "C" void kernel_launch(void* const* d_in, const int* in_sizes, int n_in,
                              void* d_out, int out_size)
{
    (void)in_sizes; (void)n_in; (void)out_size;
    const float* x   = (const float*)d_in[0];
    const float* wq  = (const float*)d_in[1];
    const float* wk  = (const float*)d_in[2];
    const float* wv  = (const float*)d_in[3];
    const float* wo  = (const float*)d_in[4];
    const float* bo  = (const float*)d_in[5];
    const float* w1  = (const float*)d_in[6];
    const float* b1  = (const float*)d_in[7];
    const float* w2  = (const float*)d_in[8];
    const float* b2  = (const float*)d_in[9];
    const float* g1  = (const float*)d_in[10];
    const float* be1 = (const float*)d_in[11];
    const float* g2  = (const float*)d_in[12];
    const float* be2 = (const float*)d_in[13];
    float* out = (float*)d_out;

    __nv_bfloat16* hb  = dev_ptr_t<__nv_bfloat16>(g_hb);
    float* qb          = dev_ptr_t<float>(g_q);
    float* kb          = dev_ptr_t<float>(g_k);
    float* vb          = dev_ptr_t<float>(g_v);
    __nv_bfloat16* ctxb = dev_ptr_t<__nv_bfloat16>(g_ctxb);
    float* x1          = dev_ptr_t<float>(g_x1);
    __nv_bfloat16* ffb = dev_ptr_t<__nv_bfloat16>(g_ffb);
    __nv_bfloat16* wqT = dev_ptr_t<__nv_bfloat16>(g_wqT);
    __nv_bfloat16* wkT = dev_ptr_t<__nv_bfloat16>(g_wkT);
    __nv_bfloat16* wvT = dev_ptr_t<__nv_bfloat16>(g_wvT);
    __nv_bfloat16* woT = dev_ptr_t<__nv_bfloat16>(g_woT);
    __nv_bfloat16* w1T = dev_ptr_t<__nv_bfloat16>(g_w1T);
    __nv_bfloat16* w2T = dev_ptr_t<__nv_bfloat16>(g_w2T);

    cudaFuncSetAttribute(attn_mma_kernel, cudaFuncAttributeMaxDynamicSharedMemorySize, ATTN_SMEM);
    cudaFuncSetAttribute(qkv_gemm_kernel,
                         cudaFuncAttributeMaxDynamicSharedMemorySize, GEMM_SMEM);
    cudaFuncSetAttribute(bf16_gemm_kernel<false, true, true, false>,
                         cudaFuncAttributeMaxDynamicSharedMemorySize, GEMM_SMEM);
    cudaFuncSetAttribute(bf16_gemm_kernel<true, true, false, true>,
                         cudaFuncAttributeMaxDynamicSharedMemorySize, GEMM_SMEM);

    transpose_all_kernel<<<1728, dim3(32, 8)>>>(wq, wk, wv, wo, w1, w2,
                                                wqT, wkT, wvT, woT, w1T, w2T);
    ln_kernel<<<NTOK / 8, 256>>>(x, g1, be1, hb);
    qkv_gemm_kernel<<<dim3(NTOK / 128, 9), 256, GEMM_SMEM>>>(hb, wqT, wkT, wvT, qb, kb, vb);
    attn_mma_kernel<<<dim3(SEQ / 64, NHEAD, BATCH), 128, ATTN_SMEM>>>(qb, kb, vb, ctxb);
    bf16_gemm_kernel<false, true, true, false><<<dim3(NTOK / 128, 3), 256, GEMM_SMEM>>>(
        ctxb, woT, bo, x, x1, DIM, DIM);
    ln_kernel<<<NTOK / 8, 256>>>(x1, g2, be2, hb);
    bf16_gemm_kernel<true, true, false, true><<<dim3(NTOK / 128, 12), 256, GEMM_SMEM>>>(
        hb, w1T, b1, nullptr, ffb, DIM, FFDIM);
    bf16_gemm_kernel<false, true, true, false><<<dim3(NTOK / 128, 3), 256, GEMM_SMEM>>>(
        ffb, w2T, b2, x1, out, FFDIM, DIM);
}